// round 11
// baseline (speedup 1.0000x reference)
#include <cuda_runtime.h>
#include <cstdint>
#include <cstddef>

// ---------------- problem constants ----------------
#define B_      128
#define C_      64
#define HW_     3136
#define M_      6
#define D_      192
#define ROWS_   48          // heads*M
#define NSPLIT  4
#define LEN_    784         // HW_/NSPLIT
#define TILE_N  112         // 784 = 7*112 -> no tail masking ever
#define NTILES  7
#define NEG_INF (-3.0e38f)

// ---- attn smem word-strides (32-bit words; chosen for conflict-free MMA LDS)
#define XCW  60             // xs_cn [64][60]  bank = 28*lq+lr (distinct)
#define XNW  36             // xs_nc [112][36] bank = 4*lq+lr  (distinct)
#define SSTR 114            // ss (f32 S) [48][114]
#define PSW  68             // ps (bf16 P) [48][68] bank = 4*lq+lr (distinct)

#define SMEM_WORDS (64*XCW + 112*XNW + ROWS_*SSTR + ROWS_*PSW + 3*ROWS_)
#define SMEM_BYTES (SMEM_WORDS * 4)

// qproj dynamic smem: z tile 32*192 + Wq tile 192*64 floats = 72 KB
#define QP_SMEM_BYTES ((32*192 + 192*64) * 4)

// ---------------- scratch ----------------
__device__ float g_qbuf[B_ * ROWS_ * C_];
__device__ float g_pm[B_ * ROWS_ * NSPLIT];
__device__ float g_pl[B_ * ROWS_ * NSPLIT];
__device__ float g_po[(size_t)B_ * ROWS_ * NSPLIT * C_];

typedef unsigned int uint32;

__device__ __forceinline__ uint32 packbf(float lo, float hi) {
    uint32 d; asm("cvt.rn.bf16x2.f32 %0, %1, %2;" : "=r"(d) : "f"(hi), "f"(lo)); return d;
}
__device__ __forceinline__ uint32 prmt(uint32 a, uint32 b, uint32 sel) {
    uint32 d; asm("prmt.b32 %0, %1, %2, %3;" : "=r"(d) : "r"(a), "r"(b), "r"(sel)); return d;
}
// D(16x8,f32) += A(16x16,bf16) @ B(16x8,bf16)
__device__ __forceinline__ void mma_bf16(float* d, const uint32* a, uint32 b0, uint32 b1) {
    asm("mma.sync.aligned.m16n8k16.row.col.f32.bf16.bf16.f32 "
        "{%0,%1,%2,%3}, {%4,%5,%6,%7}, {%8,%9}, {%0,%1,%2,%3};"
        : "+f"(d[0]), "+f"(d[1]), "+f"(d[2]), "+f"(d[3])
        : "r"(a[0]), "r"(a[1]), "r"(a[2]), "r"(a[3]), "r"(b0), "r"(b1));
}

// ---- no-op launch: keeps ncu sampling window aligned ----
__global__ void noop_kernel() {}

// ============================================================================
// Kernel 1: q = (z @ Wq + bq) * 0.125 (unchanged from R9: tiled smem GEMM).
// ============================================================================
__global__ void __launch_bounds__(256) qproj_kernel(
    const float* __restrict__ z, const float* __restrict__ Wq,
    const float* __restrict__ bq)
{
    extern __shared__ float qsm[];
    float* zsh = qsm;                     // [32][192]
    float* wsh = qsm + 32 * 192;          // [192][64]
    const int t  = threadIdx.x;
    const int e0 = blockIdx.x * 32;
    const int d0 = blockIdx.y * 64;

#pragma unroll
    for (int it = 0; it < 6; it++) {
        int idx = (t + it * 256) * 4;
        *(float4*)&zsh[idx] = *(const float4*)&z[(size_t)e0 * 192 + idx];
    }
#pragma unroll
    for (int it = 0; it < 12; it++) {
        int idx = t + it * 256;
        int k = idx >> 4, c4 = (idx & 15) * 4;
        *(float4*)&wsh[k * 64 + c4] = *(const float4*)&Wq[(size_t)k * 512 + d0 + c4];
    }
    __syncthreads();

    const int r0 = (t >> 5) * 4;
    const int d  = (t & 31) * 2;
    float acc[4][2];
#pragma unroll
    for (int i = 0; i < 4; i++) { acc[i][0] = 0.f; acc[i][1] = 0.f; }

#pragma unroll 4
    for (int k = 0; k < 192; k++) {
        float2 w = *(const float2*)&wsh[k * 64 + d];
#pragma unroll
        for (int i = 0; i < 4; i++) {
            float zv = zsh[(r0 + i) * 192 + k];
            acc[i][0] += zv * w.x;
            acc[i][1] += zv * w.y;
        }
    }
    float2 bv = *(const float2*)&bq[d0 + d];
#pragma unroll
    for (int i = 0; i < 4; i++) {
        float2 o;
        o.x = (acc[i][0] + bv.x) * 0.125f;
        o.y = (acc[i][1] + bv.y) * 0.125f;
        *(float2*)&g_qbuf[(size_t)(e0 + r0 + i) * 512 + d0 + d] = o;
    }
}

// ============================================================================
// Kernel 2: fused flash attention, bf16 mma.sync.m16n8k16.
// grid (NSPLIT, B), 192 threads = 6 warps, occ 3 (smem 65.4 KB).
// xs_cn [c][n-pair words] feeds phase3 B; xs_nc [n][c-pair words] (built by an
// in-smem PRMT transpose) feeds phase1 B; P stored bf16 [r][n-pair words].
// All MMA-operand LDS are bank-conflict-free by stride choice.
// ============================================================================
__global__ void __launch_bounds__(192, 3) attn_kernel(const float* __restrict__ x)
{
    extern __shared__ float sm[];
    uint32* xcn = (uint32*)sm;               // [64][XCW]
    uint32* xnc = xcn + 64 * XCW;            // [112][XNW]
    float*  ss  = (float*)(xnc + 112 * XNW); // [48][SSTR] f32 S
    uint32* ps  = (uint32*)(ss + ROWS_ * SSTR); // [48][PSW] bf16 P
    float*  smm = (float*)(ps + ROWS_ * PSW);
    float*  sml = smm + ROWS_;
    float*  smc = sml + ROWS_;

    const int t     = threadIdx.x;
    const int w     = t >> 5;
    const int lane  = t & 31;
    const int split = blockIdx.x;
    const int b     = blockIdx.y;
    const int n0    = split * LEN_;
    const int rg    = w >> 1;            // 16-row group
    const int half  = w & 1;             // n-half (p1) / c-half (p3)
    const int lq    = lane >> 2;         // 0..7
    const int lr    = lane & 3;          // 0..3

    // ---- Q fragments (bf16, persist across tiles). q[b][r*64+c], r=h*6+m ----
    uint32 aQ[4][4];
    {
        const float* qb = g_qbuf + (size_t)b * (ROWS_ * C_);
        int r0 = rg * 16 + lq;
#pragma unroll
        for (int kc = 0; kc < 4; kc++) {
            int k = kc * 16 + 2 * lr;
            aQ[kc][0] = packbf(qb[r0 * 64 + k],           qb[r0 * 64 + k + 1]);
            aQ[kc][1] = packbf(qb[(r0 + 8) * 64 + k],     qb[(r0 + 8) * 64 + k + 1]);
            aQ[kc][2] = packbf(qb[r0 * 64 + k + 8],       qb[r0 * 64 + k + 9]);
            aQ[kc][3] = packbf(qb[(r0 + 8) * 64 + k + 8], qb[(r0 + 8) * 64 + k + 9]);
        }
    }

    if (t < ROWS_) { smm[t] = NEG_INF; sml[t] = 0.f; }

    float oacc[4][4];
#pragma unroll
    for (int nc = 0; nc < 4; nc++)
#pragma unroll
        for (int j = 0; j < 4; j++) oacc[nc][j] = 0.f;
    __syncthreads();

    for (int tile = 0; tile < NTILES; tile++) {
        const int t0 = tile * TILE_N;

        // ---- load x tile [64][112] f32 -> bf16 pairs into xs_cn ----
#pragma unroll
        for (int it = 0; it < 10; it++) {
            int idx = t + it * 192;                 // float4 index, < 1792
            if (idx < 1792) {
                int c = idx / 28, j = idx % 28;     // j = n-quad
                float4 v = *(const float4*)&x[((size_t)b * C_ + c) * HW_ + n0 + t0 + j * 4];
                uint2 u;
                u.x = packbf(v.x, v.y);
                u.y = packbf(v.z, v.w);
                *(uint2*)&xcn[c * XCW + j * 2] = u;
            }
        }
        __syncthreads();

        // ---- transpose pass: xs_cn -> xs_nc (c-pairs per word) via PRMT ----
#pragma unroll
        for (int it = 0; it < 10; it++) {
            int idx = t + it * 192;                 // < 32*56 = 1792
            if (idx < 1792) {
                int cp = idx / 56, j = idx % 56;    // c-pair, n-pair word
                uint32 w1 = xcn[(2 * cp) * XCW + j];
                uint32 w2 = xcn[(2 * cp + 1) * XCW + j];
                xnc[(2 * j) * XNW + cp]     = prmt(w1, w2, 0x5410);
                xnc[(2 * j + 1) * XNW + cp] = prmt(w1, w2, 0x7632);
            }
        }
        __syncthreads();

        // ---- phase 1: S = Q @ Xtile (bf16 mma, K=64 -> 4 chunks) ----
        {
            const int nb = half * 56;
            float sacc[7][4];
#pragma unroll
            for (int nc = 0; nc < 7; nc++)
#pragma unroll
                for (int j = 0; j < 4; j++) sacc[nc][j] = 0.f;

#pragma unroll
            for (int kc = 0; kc < 4; kc++) {
#pragma unroll
                for (int nc = 0; nc < 7; nc++) {
                    int bn = nb + nc * 8 + lq;       // n (B col)
                    uint32 b0 = xnc[bn * XNW + kc * 8 + lr];
                    uint32 b1 = xnc[bn * XNW + kc * 8 + 4 + lr];
                    mma_bf16(sacc[nc], aQ[kc], b0, b1);
                }
            }
            int sr = rg * 16 + lq;
            int sn = nb + 2 * lr;
#pragma unroll
            for (int nc = 0; nc < 7; nc++) {
                *(float2*)&ss[sr * SSTR + sn + nc * 8] =
                    make_float2(sacc[nc][0], sacc[nc][1]);
                *(float2*)&ss[(sr + 8) * SSTR + sn + nc * 8] =
                    make_float2(sacc[nc][2], sacc[nc][3]);
            }
        }
        __syncthreads();

        // ---- phase 2: online softmax; P written as bf16 n-pairs ----
        {
#pragma unroll
            for (int i = 0; i < 8; i++) {
                int r = w * 8 + i;
                float2 v01 = *(const float2*)&ss[r * SSTR + 2 * lane];
                float v2 = NEG_INF, v3 = NEG_INF;
                if (lane < 24) {
                    float2 vt = *(const float2*)&ss[r * SSTR + 64 + 2 * lane];
                    v2 = vt.x; v3 = vt.y;
                }
                float ml = fmaxf(fmaxf(v01.x, v01.y), fmaxf(v2, v3));
#pragma unroll
                for (int off = 16; off; off >>= 1)
                    ml = fmaxf(ml, __shfl_xor_sync(0xffffffffu, ml, off));
                float mprev = smm[r];
                float mnew  = fmaxf(mprev, ml);
                float cr    = __expf(mprev - mnew);
                float p0 = __expf(v01.x - mnew);
                float p1 = __expf(v01.y - mnew);
                float p2 = __expf(v2 - mnew);       // lane>=24: exp(-huge)=0
                float p3 = __expf(v3 - mnew);
                ps[r * PSW + lane] = packbf(p0, p1);
                if (lane < 24) ps[r * PSW + 32 + lane] = packbf(p2, p3);
                float sl = (p0 + p1) + (p2 + p3);
#pragma unroll
                for (int off = 16; off; off >>= 1)
                    sl += __shfl_xor_sync(0xffffffffu, sl, off);
                if (lane == 0) {
                    sml[r] = sml[r] * cr + sl;
                    smm[r] = mnew;
                    smc[r] = cr;
                }
            }
        }
        __syncthreads();

        // ---- phase 3: O += P @ Xtile^T (bf16 mma, K=112 -> 7 chunks) ----
        {
            float cr0 = smc[rg * 16 + lq];
            float cr8 = smc[rg * 16 + 8 + lq];
#pragma unroll
            for (int nc = 0; nc < 4; nc++) {
                oacc[nc][0] *= cr0; oacc[nc][1] *= cr0;
                oacc[nc][2] *= cr8; oacc[nc][3] *= cr8;
            }
            const int cb = half * 32;
            const int sr = rg * 16 + lq;
#pragma unroll
            for (int kc = 0; kc < 7; kc++) {
                uint32 a[4];
                a[0] = ps[sr * PSW + kc * 8 + lr];
                a[1] = ps[(sr + 8) * PSW + kc * 8 + lr];
                a[2] = ps[sr * PSW + kc * 8 + 4 + lr];
                a[3] = ps[(sr + 8) * PSW + kc * 8 + 4 + lr];
#pragma unroll
                for (int nc = 0; nc < 4; nc++) {
                    int c = cb + nc * 8 + lq;
                    uint32 b0 = xcn[c * XCW + kc * 8 + lr];
                    uint32 b1 = xcn[c * XCW + kc * 8 + 4 + lr];
                    mma_bf16(oacc[nc], a, b0, b1);
                }
            }
        }
        __syncthreads();
    }

    // ---- epilogue: write split partials ----
    {
        const int cb = half * 32;
        int r0 = rg * 16 + lq;
        size_t base0 = ((size_t)(b * ROWS_ + r0) * NSPLIT + split) * C_;
        size_t base8 = ((size_t)(b * ROWS_ + r0 + 8) * NSPLIT + split) * C_;
#pragma unroll
        for (int nc = 0; nc < 4; nc++) {
            int c = cb + nc * 8 + 2 * lr;
            *(float2*)&g_po[base0 + c] = make_float2(oacc[nc][0], oacc[nc][1]);
            *(float2*)&g_po[base8 + c] = make_float2(oacc[nc][2], oacc[nc][3]);
        }
    }
    if (t < ROWS_) {
        g_pm[(b * ROWS_ + t) * NSPLIT + split] = smm[t];
        g_pl[(b * ROWS_ + t) * NSPLIT + split] = sml[t];
    }
}

// ============================================================================
// Kernel 3: combine splits + out = res @ Wo + bo + z.
// 192 CTAs x 192 thr; thread = one d-column x 4 rows (Wo loaded once per
// 4 rows, coalesced LDG; res via broadcast LDS.128; i unrolled x4 for MLP).
// ============================================================================
__global__ void __launch_bounds__(192) outproj_kernel(
    const float* __restrict__ z, const float* __restrict__ Wo,
    const float* __restrict__ bo, float* __restrict__ out)
{
    __shared__ float res[4 * 512];
    __shared__ float cw[32][5];
    const int t  = threadIdx.x;
    const int e0 = blockIdx.x * 4;

    if (t < 32) {                         // per (row, head) combine scalars
        int rl = t >> 3, h = t & 7;
        int e = e0 + rl;
        int bb = e / 6, m = e % 6;
        int base = (bb * ROWS_ + h * 6 + m) * NSPLIT;
        float m0 = g_pm[base], m1 = g_pm[base + 1], m2 = g_pm[base + 2], m3 = g_pm[base + 3];
        float Mx = fmaxf(fmaxf(m0, m1), fmaxf(m2, m3));
        float w0 = __expf(m0 - Mx), w1 = __expf(m1 - Mx);
        float w2 = __expf(m2 - Mx), w3 = __expf(m3 - Mx);
        float L = g_pl[base] * w0 + g_pl[base + 1] * w1
                + g_pl[base + 2] * w2 + g_pl[base + 3] * w3;
        cw[t][0] = w0; cw[t][1] = w1; cw[t][2] = w2; cw[t][3] = w3;
        cw[t][4] = 1.0f / L;
    }
    __syncthreads();

    // combine: res[rl][h*64+c], transpose res[b][m][h*64+c] = O[b][h*6+m][c]
#pragma unroll
    for (int k = 0; k < 11; k++) {
        int idx = t + k * 192;
        if (idx < 2048) {
            int rl = idx >> 9, j = idx & 511;
            int h = j >> 6, c = j & 63;
            int e = e0 + rl;
            int bb = e / 6, m = e % 6;
            size_t base = (size_t)((bb * ROWS_ + h * 6 + m) * NSPLIT) * C_;
            float w0 = cw[rl * 8 + h][0], w1 = cw[rl * 8 + h][1];
            float w2 = cw[rl * 8 + h][2], w3 = cw[rl * 8 + h][3];
            float ri = cw[rl * 8 + h][4];
            float v = g_po[base + c] * w0 + g_po[base + C_ + c] * w1
                    + g_po[base + 2 * C_ + c] * w2 + g_po[base + 3 * C_ + c] * w3;
            res[idx] = v * ri;
        }
    }
    __syncthreads();

    // GEMM: thread t = column d, 4 rows; w reused across rows
    const int d = t;
    float acc[4];
#pragma unroll
    for (int r = 0; r < 4; r++)
        acc[r] = bo[d] + z[(size_t)(e0 + r) * D_ + d];

    for (int i0 = 0; i0 < 512; i0 += 4) {
        float w0 = Wo[(size_t)i0 * D_ + d];
        float w1 = Wo[(size_t)(i0 + 1) * D_ + d];
        float w2 = Wo[(size_t)(i0 + 2) * D_ + d];
        float w3 = Wo[(size_t)(i0 + 3) * D_ + d];
#pragma unroll
        for (int r = 0; r < 4; r++) {
            float4 rv = *(const float4*)&res[r * 512 + i0];
            acc[r] += rv.x * w0 + rv.y * w1 + rv.z * w2 + rv.w * w3;
        }
    }
#pragma unroll
    for (int r = 0; r < 4; r++)
        out[(size_t)(e0 + r) * D_ + d] = acc[r];
}

// ============================================================================
extern "C" void kernel_launch(void* const* d_in, const int* in_sizes, int n_in,
                              void* d_out, int out_size)
{
    (void)in_sizes; (void)n_in; (void)out_size;
    const float* x  = (const float*)d_in[0];
    const float* z  = (const float*)d_in[1];
    const float* Wq = (const float*)d_in[2];
    const float* bq = (const float*)d_in[3];
    const float* Wo = (const float*)d_in[4];
    const float* bo = (const float*)d_in[5];
    float* out = (float*)d_out;

    cudaFuncSetAttribute(attn_kernel,  cudaFuncAttributeMaxDynamicSharedMemorySize, SMEM_BYTES);
    cudaFuncSetAttribute(qproj_kernel, cudaFuncAttributeMaxDynamicSharedMemorySize, QP_SMEM_BYTES);

    noop_kernel<<<1, 32>>>();
    qproj_kernel<<<dim3(24, 8), 256, QP_SMEM_BYTES>>>(z, Wq, bq);
    attn_kernel<<<dim3(NSPLIT, B_), 192, SMEM_BYTES>>>(x);
    outproj_kernel<<<192, 192>>>(z, Wo, bo, out);
}

// round 12
// speedup vs baseline: 1.2921x; 1.2921x over previous
#include <cuda_runtime.h>
#include <cstdint>
#include <cstddef>

// ---------------- problem constants ----------------
#define B_      128
#define C_      64
#define HW_     3136
#define M_      6
#define D_      192
#define ROWS_   48          // heads*M
#define NSPLIT  4
#define LEN_    784         // HW_/NSPLIT
#define TILE_N  112         // 784 = 7*112 -> no tail masking ever
#define NTILES  7
#define NEG_INF (-3.0e38f)

// ---- attn smem word-strides (32-bit words; chosen for conflict-free MMA LDS)
#define XCW  60             // xs_cn [64][60]
#define XNW  36             // xs_nc [112][36]
#define SSTR 114            // ss (f32 S) [48][114]
#define PSW  68             // ps (bf16 P) [48][68]

#define SMEM_WORDS (64*XCW + 112*XNW + ROWS_*SSTR + ROWS_*PSW + 3*ROWS_)
#define SMEM_BYTES (SMEM_WORDS * 4)

// qproj dynamic smem: z tile 32*192 + Wq tile 192*64 floats = 72 KB
#define QP_SMEM_BYTES ((32*192 + 192*64) * 4)
// outproj dynamic smem: res 16*512 + Wo chunk 128*64 + cw 128*5 = ~68 KB
#define OP_SMEM_BYTES ((16*512 + 128*64 + 128*5) * 4)

// ---------------- scratch ----------------
__device__ float g_qbuf[B_ * ROWS_ * C_];
__device__ float g_pm[B_ * ROWS_ * NSPLIT];
__device__ float g_pl[B_ * ROWS_ * NSPLIT];
__device__ float g_po[(size_t)B_ * ROWS_ * NSPLIT * C_];

typedef unsigned int uint32;

__device__ __forceinline__ uint32 packbf(float lo, float hi) {
    uint32 d; asm("cvt.rn.bf16x2.f32 %0, %1, %2;" : "=r"(d) : "f"(hi), "f"(lo)); return d;
}
__device__ __forceinline__ uint32 prmt(uint32 a, uint32 b, uint32 sel) {
    uint32 d; asm("prmt.b32 %0, %1, %2, %3;" : "=r"(d) : "r"(a), "r"(b), "r"(sel)); return d;
}
// D(16x8,f32) += A(16x16,bf16) @ B(16x8,bf16)
__device__ __forceinline__ void mma_bf16(float* d, const uint32* a, uint32 b0, uint32 b1) {
    asm("mma.sync.aligned.m16n8k16.row.col.f32.bf16.bf16.f32 "
        "{%0,%1,%2,%3}, {%4,%5,%6,%7}, {%8,%9}, {%0,%1,%2,%3};"
        : "+f"(d[0]), "+f"(d[1]), "+f"(d[2]), "+f"(d[3])
        : "r"(a[0]), "r"(a[1]), "r"(a[2]), "r"(a[3]), "r"(b0), "r"(b1));
}

// ---- no-op launches: put attn_kernel at harness launch index 5 for ncu -s5c1
__global__ void noop_kernel() {}

// ============================================================================
// Kernel 1: q = (z @ Wq + bq) * 0.125 (unchanged: tiled smem GEMM).
// ============================================================================
__global__ void __launch_bounds__(256) qproj_kernel(
    const float* __restrict__ z, const float* __restrict__ Wq,
    const float* __restrict__ bq)
{
    extern __shared__ float qsm[];
    float* zsh = qsm;                     // [32][192]
    float* wsh = qsm + 32 * 192;          // [192][64]
    const int t  = threadIdx.x;
    const int e0 = blockIdx.x * 32;
    const int d0 = blockIdx.y * 64;

#pragma unroll
    for (int it = 0; it < 6; it++) {
        int idx = (t + it * 256) * 4;
        *(float4*)&zsh[idx] = *(const float4*)&z[(size_t)e0 * 192 + idx];
    }
#pragma unroll
    for (int it = 0; it < 12; it++) {
        int idx = t + it * 256;
        int k = idx >> 4, c4 = (idx & 15) * 4;
        *(float4*)&wsh[k * 64 + c4] = *(const float4*)&Wq[(size_t)k * 512 + d0 + c4];
    }
    __syncthreads();

    const int r0 = (t >> 5) * 4;
    const int d  = (t & 31) * 2;
    float acc[4][2];
#pragma unroll
    for (int i = 0; i < 4; i++) { acc[i][0] = 0.f; acc[i][1] = 0.f; }

#pragma unroll 4
    for (int k = 0; k < 192; k++) {
        float2 w = *(const float2*)&wsh[k * 64 + d];
#pragma unroll
        for (int i = 0; i < 4; i++) {
            float zv = zsh[(r0 + i) * 192 + k];
            acc[i][0] += zv * w.x;
            acc[i][1] += zv * w.y;
        }
    }
    float2 bv = *(const float2*)&bq[d0 + d];
#pragma unroll
    for (int i = 0; i < 4; i++) {
        float2 o;
        o.x = (acc[i][0] + bv.x) * 0.125f;
        o.y = (acc[i][1] + bv.y) * 0.125f;
        *(float2*)&g_qbuf[(size_t)(e0 + r0 + i) * 512 + d0 + d] = o;
    }
}

// ============================================================================
// Kernel 2: fused flash attention, bf16 mma.sync.m16n8k16 (unchanged from R11).
// grid (NSPLIT, B), 192 threads = 6 warps, occ 3.
// ============================================================================
__global__ void __launch_bounds__(192, 3) attn_kernel(const float* __restrict__ x)
{
    extern __shared__ float sm[];
    uint32* xcn = (uint32*)sm;               // [64][XCW]
    uint32* xnc = xcn + 64 * XCW;            // [112][XNW]
    float*  ss  = (float*)(xnc + 112 * XNW); // [48][SSTR] f32 S
    uint32* ps  = (uint32*)(ss + ROWS_ * SSTR); // [48][PSW] bf16 P
    float*  smm = (float*)(ps + ROWS_ * PSW);
    float*  sml = smm + ROWS_;
    float*  smc = sml + ROWS_;

    const int t     = threadIdx.x;
    const int w     = t >> 5;
    const int lane  = t & 31;
    const int split = blockIdx.x;
    const int b     = blockIdx.y;
    const int n0    = split * LEN_;
    const int rg    = w >> 1;
    const int half  = w & 1;
    const int lq    = lane >> 2;
    const int lr    = lane & 3;

    uint32 aQ[4][4];
    {
        const float* qb = g_qbuf + (size_t)b * (ROWS_ * C_);
        int r0 = rg * 16 + lq;
#pragma unroll
        for (int kc = 0; kc < 4; kc++) {
            int k = kc * 16 + 2 * lr;
            aQ[kc][0] = packbf(qb[r0 * 64 + k],           qb[r0 * 64 + k + 1]);
            aQ[kc][1] = packbf(qb[(r0 + 8) * 64 + k],     qb[(r0 + 8) * 64 + k + 1]);
            aQ[kc][2] = packbf(qb[r0 * 64 + k + 8],       qb[r0 * 64 + k + 9]);
            aQ[kc][3] = packbf(qb[(r0 + 8) * 64 + k + 8], qb[(r0 + 8) * 64 + k + 9]);
        }
    }

    if (t < ROWS_) { smm[t] = NEG_INF; sml[t] = 0.f; }

    float oacc[4][4];
#pragma unroll
    for (int nc = 0; nc < 4; nc++)
#pragma unroll
        for (int j = 0; j < 4; j++) oacc[nc][j] = 0.f;
    __syncthreads();

    for (int tile = 0; tile < NTILES; tile++) {
        const int t0 = tile * TILE_N;

#pragma unroll
        for (int it = 0; it < 10; it++) {
            int idx = t + it * 192;
            if (idx < 1792) {
                int c = idx / 28, j = idx % 28;
                float4 v = *(const float4*)&x[((size_t)b * C_ + c) * HW_ + n0 + t0 + j * 4];
                uint2 u;
                u.x = packbf(v.x, v.y);
                u.y = packbf(v.z, v.w);
                *(uint2*)&xcn[c * XCW + j * 2] = u;
            }
        }
        __syncthreads();

        // transpose pass: xs_cn -> xs_nc via PRMT
#pragma unroll
        for (int it = 0; it < 10; it++) {
            int idx = t + it * 192;
            if (idx < 1792) {
                int cp = idx / 56, j = idx % 56;
                uint32 w1 = xcn[(2 * cp) * XCW + j];
                uint32 w2 = xcn[(2 * cp + 1) * XCW + j];
                xnc[(2 * j) * XNW + cp]     = prmt(w1, w2, 0x5410);
                xnc[(2 * j + 1) * XNW + cp] = prmt(w1, w2, 0x7632);
            }
        }
        __syncthreads();

        // phase 1: S = Q @ Xtile
        {
            const int nb = half * 56;
            float sacc[7][4];
#pragma unroll
            for (int nc = 0; nc < 7; nc++)
#pragma unroll
                for (int j = 0; j < 4; j++) sacc[nc][j] = 0.f;

#pragma unroll
            for (int kc = 0; kc < 4; kc++) {
#pragma unroll
                for (int nc = 0; nc < 7; nc++) {
                    int bn = nb + nc * 8 + lq;
                    uint32 b0 = xnc[bn * XNW + kc * 8 + lr];
                    uint32 b1 = xnc[bn * XNW + kc * 8 + 4 + lr];
                    mma_bf16(sacc[nc], aQ[kc], b0, b1);
                }
            }
            int sr = rg * 16 + lq;
            int sn = nb + 2 * lr;
#pragma unroll
            for (int nc = 0; nc < 7; nc++) {
                *(float2*)&ss[sr * SSTR + sn + nc * 8] =
                    make_float2(sacc[nc][0], sacc[nc][1]);
                *(float2*)&ss[(sr + 8) * SSTR + sn + nc * 8] =
                    make_float2(sacc[nc][2], sacc[nc][3]);
            }
        }
        __syncthreads();

        // phase 2: online softmax; P written as bf16 n-pairs
        {
#pragma unroll
            for (int i = 0; i < 8; i++) {
                int r = w * 8 + i;
                float2 v01 = *(const float2*)&ss[r * SSTR + 2 * lane];
                float v2 = NEG_INF, v3 = NEG_INF;
                if (lane < 24) {
                    float2 vt = *(const float2*)&ss[r * SSTR + 64 + 2 * lane];
                    v2 = vt.x; v3 = vt.y;
                }
                float ml = fmaxf(fmaxf(v01.x, v01.y), fmaxf(v2, v3));
#pragma unroll
                for (int off = 16; off; off >>= 1)
                    ml = fmaxf(ml, __shfl_xor_sync(0xffffffffu, ml, off));
                float mprev = smm[r];
                float mnew  = fmaxf(mprev, ml);
                float cr    = __expf(mprev - mnew);
                float p0 = __expf(v01.x - mnew);
                float p1 = __expf(v01.y - mnew);
                float p2 = __expf(v2 - mnew);
                float p3 = __expf(v3 - mnew);
                ps[r * PSW + lane] = packbf(p0, p1);
                if (lane < 24) ps[r * PSW + 32 + lane] = packbf(p2, p3);
                float sl = (p0 + p1) + (p2 + p3);
#pragma unroll
                for (int off = 16; off; off >>= 1)
                    sl += __shfl_xor_sync(0xffffffffu, sl, off);
                if (lane == 0) {
                    sml[r] = sml[r] * cr + sl;
                    smm[r] = mnew;
                    smc[r] = cr;
                }
            }
        }
        __syncthreads();

        // phase 3: O += P @ Xtile^T
        {
            float cr0 = smc[rg * 16 + lq];
            float cr8 = smc[rg * 16 + 8 + lq];
#pragma unroll
            for (int nc = 0; nc < 4; nc++) {
                oacc[nc][0] *= cr0; oacc[nc][1] *= cr0;
                oacc[nc][2] *= cr8; oacc[nc][3] *= cr8;
            }
            const int cb = half * 32;
            const int sr = rg * 16 + lq;
#pragma unroll
            for (int kc = 0; kc < 7; kc++) {
                uint32 a[4];
                a[0] = ps[sr * PSW + kc * 8 + lr];
                a[1] = ps[(sr + 8) * PSW + kc * 8 + lr];
                a[2] = ps[sr * PSW + kc * 8 + 4 + lr];
                a[3] = ps[(sr + 8) * PSW + kc * 8 + 4 + lr];
#pragma unroll
                for (int nc = 0; nc < 4; nc++) {
                    int c = cb + nc * 8 + lq;
                    uint32 b0 = xcn[c * XCW + kc * 8 + lr];
                    uint32 b1 = xcn[c * XCW + kc * 8 + 4 + lr];
                    mma_bf16(oacc[nc], a, b0, b1);
                }
            }
        }
        __syncthreads();
    }

    {
        const int cb = half * 32;
        int r0 = rg * 16 + lq;
        size_t base0 = ((size_t)(b * ROWS_ + r0) * NSPLIT + split) * C_;
        size_t base8 = ((size_t)(b * ROWS_ + r0 + 8) * NSPLIT + split) * C_;
#pragma unroll
        for (int nc = 0; nc < 4; nc++) {
            int c = cb + nc * 8 + 2 * lr;
            *(float2*)&g_po[base0 + c] = make_float2(oacc[nc][0], oacc[nc][1]);
            *(float2*)&g_po[base8 + c] = make_float2(oacc[nc][2], oacc[nc][3]);
        }
    }
    if (t < ROWS_) {
        g_pm[(b * ROWS_ + t) * NSPLIT + split] = smm[t];
        g_pl[(b * ROWS_ + t) * NSPLIT + split] = sml[t];
    }
}

// ============================================================================
// Kernel 3: combine splits + out = res @ Wo + bo + z.
// Tiled smem GEMM (qproj pattern): grid (48 rowblocks x 3 dblocks) = 144 CTAs,
// 256 thr. res tile [16][512] + Wo chunk [128][64] in dynamic smem; K=512 in
// 4 chunks so the k-loop never touches global. Thread tile 2r x 2d.
// ============================================================================
__global__ void __launch_bounds__(256) outproj_kernel(
    const float* __restrict__ z, const float* __restrict__ Wo,
    const float* __restrict__ bo, float* __restrict__ out)
{
    extern __shared__ float osm[];
    float* res = osm;                 // [16][512]
    float* wsh = osm + 16 * 512;      // [128][64]
    float* cw  = wsh + 128 * 64;      // [128][5]
    const int t  = threadIdx.x;
    const int e0 = blockIdx.x * 16;
    const int d0 = blockIdx.y * 64;

    if (t < 128) {                    // per (row, head) combine scalars
        int rl = t >> 3, h = t & 7;
        int e = e0 + rl;
        int bb = e / 6, m = e % 6;
        int base = (bb * ROWS_ + h * 6 + m) * NSPLIT;
        float m0 = g_pm[base], m1 = g_pm[base + 1], m2 = g_pm[base + 2], m3 = g_pm[base + 3];
        float Mx = fmaxf(fmaxf(m0, m1), fmaxf(m2, m3));
        float w0 = __expf(m0 - Mx), w1 = __expf(m1 - Mx);
        float w2 = __expf(m2 - Mx), w3 = __expf(m3 - Mx);
        float L = g_pl[base] * w0 + g_pl[base + 1] * w1
                + g_pl[base + 2] * w2 + g_pl[base + 3] * w3;
        cw[t * 5 + 0] = w0; cw[t * 5 + 1] = w1;
        cw[t * 5 + 2] = w2; cw[t * 5 + 3] = w3;
        cw[t * 5 + 4] = 1.0f / L;
    }
    __syncthreads();

    // combine into res[rl][h*64+c] (transpose: res[b][m][h*64+c]=O[b][h*6+m][c])
#pragma unroll 4
    for (int k = 0; k < 32; k++) {
        int idx = t + k * 256;        // < 8192
        int rl = idx >> 9, j = idx & 511;
        int h = j >> 6, c = j & 63;
        int e = e0 + rl;
        int bb = e / 6, m = e % 6;
        size_t base = (size_t)((bb * ROWS_ + h * 6 + m) * NSPLIT) * C_;
        const float* cwp = &cw[(rl * 8 + h) * 5];
        float v = g_po[base + c] * cwp[0] + g_po[base + C_ + c] * cwp[1]
                + g_po[base + 2 * C_ + c] * cwp[2] + g_po[base + 3 * C_ + c] * cwp[3];
        res[idx] = v * cwp[4];
    }

    const int tr = (t >> 5) * 2;      // 2 rows per thread
    const int td = (t & 31) * 2;      // 2 cols per thread
    float acc[2][2];
    acc[0][0] = acc[0][1] = acc[1][0] = acc[1][1] = 0.f;

    for (int ko = 0; ko < 4; ko++) {
        __syncthreads();              // res complete (ko=0) / prev chunk done
#pragma unroll
        for (int it = 0; it < 8; it++) {
            int idx = t + it * 256;   // < 2048 float4s
            int k = idx >> 4, c4 = (idx & 15) * 4;
            *(float4*)&wsh[k * 64 + c4] =
                *(const float4*)&Wo[(size_t)(ko * 128 + k) * D_ + d0 + c4];
        }
        __syncthreads();
#pragma unroll 4
        for (int k = 0; k < 128; k++) {
            float2 wv = *(const float2*)&wsh[k * 64 + td];
            float r0 = res[tr * 512 + ko * 128 + k];
            float r1 = res[(tr + 1) * 512 + ko * 128 + k];
            acc[0][0] += r0 * wv.x; acc[0][1] += r0 * wv.y;
            acc[1][0] += r1 * wv.x; acc[1][1] += r1 * wv.y;
        }
    }

    float2 bv = *(const float2*)&bo[d0 + td];
#pragma unroll
    for (int i = 0; i < 2; i++) {
        float2 zv = *(const float2*)&z[(size_t)(e0 + tr + i) * D_ + d0 + td];
        float2 o;
        o.x = acc[i][0] + bv.x + zv.x;
        o.y = acc[i][1] + bv.y + zv.y;
        *(float2*)&out[(size_t)(e0 + tr + i) * D_ + d0 + td] = o;
    }
}

// ============================================================================
extern "C" void kernel_launch(void* const* d_in, const int* in_sizes, int n_in,
                              void* d_out, int out_size)
{
    (void)in_sizes; (void)n_in; (void)out_size;
    const float* x  = (const float*)d_in[0];
    const float* z  = (const float*)d_in[1];
    const float* Wq = (const float*)d_in[2];
    const float* bq = (const float*)d_in[3];
    const float* Wo = (const float*)d_in[4];
    const float* bo = (const float*)d_in[5];
    float* out = (float*)d_out;

    cudaFuncSetAttribute(attn_kernel,    cudaFuncAttributeMaxDynamicSharedMemorySize, SMEM_BYTES);
    cudaFuncSetAttribute(qproj_kernel,   cudaFuncAttributeMaxDynamicSharedMemorySize, QP_SMEM_BYTES);
    cudaFuncSetAttribute(outproj_kernel, cudaFuncAttributeMaxDynamicSharedMemorySize, OP_SMEM_BYTES);

    noop_kernel<<<1, 32>>>();   // two noops: put attn at harness launch idx 5
    noop_kernel<<<1, 32>>>();   // (ncu -s 5 -c 1 capture target)
    qproj_kernel<<<dim3(24, 8), 256, QP_SMEM_BYTES>>>(z, Wq, bq);
    attn_kernel<<<dim3(NSPLIT, B_), 192, SMEM_BYTES>>>(x);
    outproj_kernel<<<dim3(48, 3), 256, OP_SMEM_BYTES>>>(z, Wo, bo, out);
}

// round 13
// speedup vs baseline: 1.3002x; 1.0062x over previous
#include <cuda_runtime.h>
#include <cstdint>
#include <cstddef>

// ---------------- problem constants ----------------
#define B_      128
#define C_      64
#define HW_     3136
#define M_      6
#define D_      192
#define ROWS_   48          // heads*M
#define NSPLIT  4
#define LEN_    784         // HW_/NSPLIT
#define TILE_N  112         // 784 = 7*112 -> no tail masking ever
#define NTILES  7
#define NEG_INF (-3.0e38f)

// ---- attn smem word-strides (32-bit words)
#define XCW  58             // xs_cn [64][58]  (even; <=2-way on LDS.64)
#define XNW  40             // xs_nc [112][40] (even; 2-way on LDS.64)
#define SSTR 114            // ss [48][114]: f32 S, then bf16 P (reused in-place)

#define SMEM_WORDS (64*XCW + 112*XNW + ROWS_*SSTR + 3*ROWS_)
#define SMEM_BYTES (SMEM_WORDS * 4)

// qproj dynamic smem: z tile 32*192 + Wq tile 192*64 floats = 72 KB
#define QP_SMEM_BYTES ((32*192 + 192*64) * 4)
// outproj dynamic smem: res 16*512 + Wo chunk 128*64 + cw 128*5
#define OP_SMEM_BYTES ((16*512 + 128*64 + 128*5) * 4)

// group-of-8 pair interleave: logical word w -> physical slot
// (0,4,1,5,2,6,3,7) within each group of 8 so (k, k+4) pairs are adjacent.
#define ILV(w) (((w) & ~7) | ((((w) & 3) << 1) | ((((w) >> 2) & 1))))

// ---------------- scratch ----------------
__device__ float g_qbuf[B_ * ROWS_ * C_];
__device__ float g_pm[B_ * ROWS_ * NSPLIT];
__device__ float g_pl[B_ * ROWS_ * NSPLIT];
__device__ float g_po[(size_t)B_ * ROWS_ * NSPLIT * C_];

typedef unsigned int uint32;

__device__ __forceinline__ uint32 packbf(float lo, float hi) {
    uint32 d; asm("cvt.rn.bf16x2.f32 %0, %1, %2;" : "=r"(d) : "f"(hi), "f"(lo)); return d;
}
__device__ __forceinline__ uint32 prmt(uint32 a, uint32 b, uint32 sel) {
    uint32 d; asm("prmt.b32 %0, %1, %2, %3;" : "=r"(d) : "r"(a), "r"(b), "r"(sel)); return d;
}
// D(16x8,f32) += A(16x16,bf16) @ B(16x8,bf16)
__device__ __forceinline__ void mma_bf16(float* d, uint32 a0, uint32 a1, uint32 a2,
                                         uint32 a3, uint32 b0, uint32 b1) {
    asm("mma.sync.aligned.m16n8k16.row.col.f32.bf16.bf16.f32 "
        "{%0,%1,%2,%3}, {%4,%5,%6,%7}, {%8,%9}, {%0,%1,%2,%3};"
        : "+f"(d[0]), "+f"(d[1]), "+f"(d[2]), "+f"(d[3])
        : "r"(a0), "r"(a1), "r"(a2), "r"(a3), "r"(b0), "r"(b1));
}
__device__ __forceinline__ void bar_pair(int id) {
    asm volatile("bar.sync %0, 64;" :: "r"(id) : "memory");
}

// ---- no-op launches: keep attn_kernel at ncu's -s5 -c1 capture slot ----
__global__ void noop_kernel() {}

// ============================================================================
// Kernel 1: q = (z @ Wq + bq) * 0.125 (unchanged: tiled smem GEMM).
// ============================================================================
__global__ void __launch_bounds__(256) qproj_kernel(
    const float* __restrict__ z, const float* __restrict__ Wq,
    const float* __restrict__ bq)
{
    extern __shared__ float qsm[];
    float* zsh = qsm;                     // [32][192]
    float* wsh = qsm + 32 * 192;          // [192][64]
    const int t  = threadIdx.x;
    const int e0 = blockIdx.x * 32;
    const int d0 = blockIdx.y * 64;

#pragma unroll
    for (int it = 0; it < 6; it++) {
        int idx = (t + it * 256) * 4;
        *(float4*)&zsh[idx] = *(const float4*)&z[(size_t)e0 * 192 + idx];
    }
#pragma unroll
    for (int it = 0; it < 12; it++) {
        int idx = t + it * 256;
        int k = idx >> 4, c4 = (idx & 15) * 4;
        *(float4*)&wsh[k * 64 + c4] = *(const float4*)&Wq[(size_t)k * 512 + d0 + c4];
    }
    __syncthreads();

    const int r0 = (t >> 5) * 4;
    const int d  = (t & 31) * 2;
    float acc[4][2];
#pragma unroll
    for (int i = 0; i < 4; i++) { acc[i][0] = 0.f; acc[i][1] = 0.f; }

#pragma unroll 4
    for (int k = 0; k < 192; k++) {
        float2 w = *(const float2*)&wsh[k * 64 + d];
#pragma unroll
        for (int i = 0; i < 4; i++) {
            float zv = zsh[(r0 + i) * 192 + k];
            acc[i][0] += zv * w.x;
            acc[i][1] += zv * w.y;
        }
    }
    float2 bv = *(const float2*)&bq[d0 + d];
#pragma unroll
    for (int i = 0; i < 4; i++) {
        float2 o;
        o.x = (acc[i][0] + bv.x) * 0.125f;
        o.y = (acc[i][1] + bv.y) * 0.125f;
        *(float2*)&g_qbuf[(size_t)(e0 + r0 + i) * 512 + d0 + d] = o;
    }
}

// ============================================================================
// Kernel 2: fused flash attention, bf16 mma.sync.m16n8k16.
// grid (NSPLIT, B), 192 threads = 6 warps, target occ 4 (smem 55.2 KB).
// All MMA operand fetches are LDS.64 via pair-interleaved layouts (ILV).
// P reuses the S buffer (warp-synchronous in-place overwrite).
// Phase 1->2->3 sync is per warp-pair (named barriers 1+rg); full barriers
// only around the shared x tile.
// ============================================================================
__global__ void __launch_bounds__(192, 4) attn_kernel(const float* __restrict__ x)
{
    extern __shared__ float sm[];
    uint32* xcn = (uint32*)sm;               // [64][XCW]  bf16x2 n-pairs, ILV
    uint32* xnc = xcn + 64 * XCW;            // [112][XNW] bf16x2 c-pairs, ILV
    float*  ss  = (float*)(xnc + 112 * XNW); // [48][SSTR] f32 S -> bf16 P (ILV)
    float*  smm = ss + ROWS_ * SSTR;
    float*  sml = smm + ROWS_;
    float*  smc = sml + ROWS_;
    uint32* ssu = (uint32*)ss;

    const int t     = threadIdx.x;
    const int w     = t >> 5;
    const int lane  = t & 31;
    const int split = blockIdx.x;
    const int b     = blockIdx.y;
    const int n0    = split * LEN_;
    const int rg    = w >> 1;            // warp pair = 16-row group
    const int half  = w & 1;
    const int lq    = lane >> 2;
    const int lr    = lane & 3;

    // ---- Q fragments (bf16, persist). q[b][r*64+c], r = h*6+m ----
    uint32 aQ[4][4];
    {
        const float* qb = g_qbuf + (size_t)b * (ROWS_ * C_);
        int r0 = rg * 16 + lq;
#pragma unroll
        for (int kc = 0; kc < 4; kc++) {
            int k = kc * 16 + 2 * lr;
            aQ[kc][0] = packbf(qb[r0 * 64 + k],           qb[r0 * 64 + k + 1]);
            aQ[kc][1] = packbf(qb[(r0 + 8) * 64 + k],     qb[(r0 + 8) * 64 + k + 1]);
            aQ[kc][2] = packbf(qb[r0 * 64 + k + 8],       qb[r0 * 64 + k + 9]);
            aQ[kc][3] = packbf(qb[(r0 + 8) * 64 + k + 8], qb[(r0 + 8) * 64 + k + 9]);
        }
    }

    if (t < ROWS_) { smm[t] = NEG_INF; sml[t] = 0.f; }

    float oacc[4][4];
#pragma unroll
    for (int nc = 0; nc < 4; nc++)
#pragma unroll
        for (int j = 0; j < 4; j++) oacc[nc][j] = 0.f;
    __syncthreads();

    for (int tile = 0; tile < NTILES; tile++) {
        const int t0 = tile * TILE_N;

        // ---- load x tile [64][112] f32 -> bf16 pairs into xcn (ILV slots) ----
#pragma unroll
        for (int it = 0; it < 10; it++) {
            int idx = t + it * 192;                 // float4 index, < 1792
            if (idx < 1792) {
                int c = idx / 28, j = idx % 28;     // j = n-quad
                float4 v = *(const float4*)&x[((size_t)b * C_ + c) * HW_ + n0 + t0 + j * 4];
                xcn[c * XCW + ILV(2 * j)]     = packbf(v.x, v.y);
                xcn[c * XCW + ILV(2 * j + 1)] = packbf(v.z, v.w);
            }
        }
        __syncthreads();

        // ---- transpose pass: xcn -> xnc (c-pairs per word, ILV slots) ----
#pragma unroll
        for (int it = 0; it < 10; it++) {
            int idx = t + it * 192;                 // < 32*56 = 1792
            if (idx < 1792) {
                int cp = idx / 56, j = idx % 56;    // c-pair, n-pair (logical)
                uint32 w1 = xcn[(2 * cp) * XCW + ILV(j)];
                uint32 w2 = xcn[(2 * cp + 1) * XCW + ILV(j)];
                xnc[(2 * j) * XNW + ILV(cp)]     = prmt(w1, w2, 0x5410);
                xnc[(2 * j + 1) * XNW + ILV(cp)] = prmt(w1, w2, 0x7632);
            }
        }
        __syncthreads();

        // ---- phase 1: S = Q @ Xtile (LDS.64 B operands) ----
        {
            const int nb = half * 56;
            float sacc[7][4];
#pragma unroll
            for (int nc = 0; nc < 7; nc++)
#pragma unroll
                for (int j = 0; j < 4; j++) sacc[nc][j] = 0.f;

#pragma unroll
            for (int kc = 0; kc < 4; kc++) {
#pragma unroll
                for (int nc = 0; nc < 7; nc++) {
                    int bn = nb + nc * 8 + lq;
                    uint2 Bv = *(const uint2*)&xnc[bn * XNW + kc * 8 + 2 * lr];
                    mma_bf16(sacc[nc], aQ[kc][0], aQ[kc][1], aQ[kc][2], aQ[kc][3],
                             Bv.x, Bv.y);
                }
            }
            int sr = rg * 16 + lq;
            int sn = nb + 2 * lr;
#pragma unroll
            for (int nc = 0; nc < 7; nc++) {
                *(float2*)&ss[sr * SSTR + sn + nc * 8] =
                    make_float2(sacc[nc][0], sacc[nc][1]);
                *(float2*)&ss[(sr + 8) * SSTR + sn + nc * 8] =
                    make_float2(sacc[nc][2], sacc[nc][3]);
            }
        }
        bar_pair(1 + rg);     // pair-scoped: ss rows rg*16..+16

        // ---- phase 2: online softmax; P overwrites S (bf16, ILV slots) ----
        {
#pragma unroll
            for (int i = 0; i < 8; i++) {
                int r = w * 8 + i;
                float2 v01 = *(const float2*)&ss[r * SSTR + 2 * lane];
                float v2 = NEG_INF, v3 = NEG_INF;
                if (lane < 24) {
                    float2 vt = *(const float2*)&ss[r * SSTR + 64 + 2 * lane];
                    v2 = vt.x; v3 = vt.y;
                }
                float ml = fmaxf(fmaxf(v01.x, v01.y), fmaxf(v2, v3));
#pragma unroll
                for (int off = 16; off; off >>= 1)
                    ml = fmaxf(ml, __shfl_xor_sync(0xffffffffu, ml, off));
                float mprev = smm[r];
                float mnew  = fmaxf(mprev, ml);
                float cr    = __expf(mprev - mnew);
                float p0 = __expf(v01.x - mnew);
                float p1 = __expf(v01.y - mnew);
                float p2 = __expf(v2 - mnew);       // lane>=24: exp(-huge)=0
                float p3 = __expf(v3 - mnew);
                // warp-synchronous: all reads of row r above precede these writes
                ssu[r * SSTR + ILV(lane)] = packbf(p0, p1);
                if (lane < 24) ssu[r * SSTR + ILV(32 + lane)] = packbf(p2, p3);
                float sl = (p0 + p1) + (p2 + p3);
#pragma unroll
                for (int off = 16; off; off >>= 1)
                    sl += __shfl_xor_sync(0xffffffffu, sl, off);
                if (lane == 0) {
                    sml[r] = sml[r] * cr + sl;
                    smm[r] = mnew;
                    smc[r] = cr;
                }
            }
        }
        bar_pair(1 + rg);     // pair-scoped: P rows + smc for own rows

        // ---- phase 3: O += P @ Xtile^T (LDS.64 A and B operands) ----
        {
            float cr0 = smc[rg * 16 + lq];
            float cr8 = smc[rg * 16 + 8 + lq];
#pragma unroll
            for (int nc = 0; nc < 4; nc++) {
                oacc[nc][0] *= cr0; oacc[nc][1] *= cr0;
                oacc[nc][2] *= cr8; oacc[nc][3] *= cr8;
            }
            const int cb = half * 32;
            const int sr = rg * 16 + lq;
#pragma unroll
            for (int kc = 0; kc < 7; kc++) {
                uint2 A0 = *(const uint2*)&ssu[sr * SSTR + kc * 8 + 2 * lr];       // (a0,a2)
                uint2 A1 = *(const uint2*)&ssu[(sr + 8) * SSTR + kc * 8 + 2 * lr]; // (a1,a3)
#pragma unroll
                for (int nc = 0; nc < 4; nc++) {
                    int c = cb + nc * 8 + lq;
                    uint2 Bv = *(const uint2*)&xcn[c * XCW + kc * 8 + 2 * lr];
                    mma_bf16(oacc[nc], A0.x, A1.x, A0.y, A1.y, Bv.x, Bv.y);
                }
            }
        }
        __syncthreads();      // full: xcn/xnc overwritten by next tile's load
    }

    // ---- epilogue: write split partials ----
    {
        const int cb = half * 32;
        int r0 = rg * 16 + lq;
        size_t base0 = ((size_t)(b * ROWS_ + r0) * NSPLIT + split) * C_;
        size_t base8 = ((size_t)(b * ROWS_ + r0 + 8) * NSPLIT + split) * C_;
#pragma unroll
        for (int nc = 0; nc < 4; nc++) {
            int c = cb + nc * 8 + 2 * lr;
            *(float2*)&g_po[base0 + c] = make_float2(oacc[nc][0], oacc[nc][1]);
            *(float2*)&g_po[base8 + c] = make_float2(oacc[nc][2], oacc[nc][3]);
        }
    }
    if (t < ROWS_) {
        g_pm[(b * ROWS_ + t) * NSPLIT + split] = smm[t];
        g_pl[(b * ROWS_ + t) * NSPLIT + split] = sml[t];
    }
}

// ============================================================================
// Kernel 3: combine splits + out = res @ Wo + bo + z (unchanged from R12).
// ============================================================================
__global__ void __launch_bounds__(256) outproj_kernel(
    const float* __restrict__ z, const float* __restrict__ Wo,
    const float* __restrict__ bo, float* __restrict__ out)
{
    extern __shared__ float osm[];
    float* res = osm;                 // [16][512]
    float* wsh = osm + 16 * 512;      // [128][64]
    float* cw  = wsh + 128 * 64;      // [128][5]
    const int t  = threadIdx.x;
    const int e0 = blockIdx.x * 16;
    const int d0 = blockIdx.y * 64;

    if (t < 128) {
        int rl = t >> 3, h = t & 7;
        int e = e0 + rl;
        int bb = e / 6, m = e % 6;
        int base = (bb * ROWS_ + h * 6 + m) * NSPLIT;
        float m0 = g_pm[base], m1 = g_pm[base + 1], m2 = g_pm[base + 2], m3 = g_pm[base + 3];
        float Mx = fmaxf(fmaxf(m0, m1), fmaxf(m2, m3));
        float w0 = __expf(m0 - Mx), w1 = __expf(m1 - Mx);
        float w2 = __expf(m2 - Mx), w3 = __expf(m3 - Mx);
        float L = g_pl[base] * w0 + g_pl[base + 1] * w1
                + g_pl[base + 2] * w2 + g_pl[base + 3] * w3;
        cw[t * 5 + 0] = w0; cw[t * 5 + 1] = w1;
        cw[t * 5 + 2] = w2; cw[t * 5 + 3] = w3;
        cw[t * 5 + 4] = 1.0f / L;
    }
    __syncthreads();

#pragma unroll 4
    for (int k = 0; k < 32; k++) {
        int idx = t + k * 256;        // < 8192
        int rl = idx >> 9, j = idx & 511;
        int h = j >> 6, c = j & 63;
        int e = e0 + rl;
        int bb = e / 6, m = e % 6;
        size_t base = (size_t)((bb * ROWS_ + h * 6 + m) * NSPLIT) * C_;
        const float* cwp = &cw[(rl * 8 + h) * 5];
        float v = g_po[base + c] * cwp[0] + g_po[base + C_ + c] * cwp[1]
                + g_po[base + 2 * C_ + c] * cwp[2] + g_po[base + 3 * C_ + c] * cwp[3];
        res[idx] = v * cwp[4];
    }

    const int tr = (t >> 5) * 2;
    const int td = (t & 31) * 2;
    float acc[2][2];
    acc[0][0] = acc[0][1] = acc[1][0] = acc[1][1] = 0.f;

    for (int ko = 0; ko < 4; ko++) {
        __syncthreads();
#pragma unroll
        for (int it = 0; it < 8; it++) {
            int idx = t + it * 256;
            int k = idx >> 4, c4 = (idx & 15) * 4;
            *(float4*)&wsh[k * 64 + c4] =
                *(const float4*)&Wo[(size_t)(ko * 128 + k) * D_ + d0 + c4];
        }
        __syncthreads();
#pragma unroll 4
        for (int k = 0; k < 128; k++) {
            float2 wv = *(const float2*)&wsh[k * 64 + td];
            float r0 = res[tr * 512 + ko * 128 + k];
            float r1 = res[(tr + 1) * 512 + ko * 128 + k];
            acc[0][0] += r0 * wv.x; acc[0][1] += r0 * wv.y;
            acc[1][0] += r1 * wv.x; acc[1][1] += r1 * wv.y;
        }
    }

    float2 bv = *(const float2*)&bo[d0 + td];
#pragma unroll
    for (int i = 0; i < 2; i++) {
        float2 zv = *(const float2*)&z[(size_t)(e0 + tr + i) * D_ + d0 + td];
        float2 o;
        o.x = acc[i][0] + bv.x + zv.x;
        o.y = acc[i][1] + bv.y + zv.y;
        *(float2*)&out[(size_t)(e0 + tr + i) * D_ + d0 + td] = o;
    }
}

// ============================================================================
extern "C" void kernel_launch(void* const* d_in, const int* in_sizes, int n_in,
                              void* d_out, int out_size)
{
    (void)in_sizes; (void)n_in; (void)out_size;
    const float* x  = (const float*)d_in[0];
    const float* z  = (const float*)d_in[1];
    const float* Wq = (const float*)d_in[2];
    const float* bq = (const float*)d_in[3];
    const float* Wo = (const float*)d_in[4];
    const float* bo = (const float*)d_in[5];
    float* out = (float*)d_out;

    cudaFuncSetAttribute(attn_kernel,    cudaFuncAttributeMaxDynamicSharedMemorySize, SMEM_BYTES);
    cudaFuncSetAttribute(qproj_kernel,   cudaFuncAttributeMaxDynamicSharedMemorySize, QP_SMEM_BYTES);
    cudaFuncSetAttribute(outproj_kernel, cudaFuncAttributeMaxDynamicSharedMemorySize, OP_SMEM_BYTES);

    noop_kernel<<<1, 32>>>();
    noop_kernel<<<1, 32>>>();
    qproj_kernel<<<dim3(24, 8), 256, QP_SMEM_BYTES>>>(z, Wq, bq);
    attn_kernel<<<dim3(NSPLIT, B_), 192, SMEM_BYTES>>>(x);
    outproj_kernel<<<dim3(48, 3), 256, OP_SMEM_BYTES>>>(z, Wo, bo, out);
}

// round 16
// speedup vs baseline: 1.5968x; 1.2281x over previous
#include <cuda_runtime.h>
#include <cstdint>
#include <cstddef>

// ---------------- problem constants ----------------
#define B_      128
#define C_      64
#define HW_     3136
#define M_      6
#define D_      192
#define ROWS_   48          // heads*M
#define NSPLIT  4
#define LEN_    784         // HW_/NSPLIT
#define TILE_N  112         // 784 = 7*112 -> no tail masking ever
#define NTILES  7
#define NEG_INF (-3.0e38f)

// ---- attn smem word-strides (32-bit words)
#define XCW  58             // xs_cn [64][58]
#define XNW  40             // xs_nc [112][40]
#define PSW  72             // ps (bf16 P) [48][72]

#define SMEM_WORDS (64*XCW + 112*XNW + ROWS_*PSW + 2*2*ROWS_)
#define SMEM_BYTES (SMEM_WORDS * 4)

// qproj dynamic smem: z tile 32*192 + Wq tile 192*64 floats = 72 KB
#define QP_SMEM_BYTES ((32*192 + 192*64) * 4)
// outproj dynamic smem: res 16*512 + Wo chunk 128*64 + cw 128*5
#define OP_SMEM_BYTES ((16*512 + 128*64 + 128*5) * 4)

// group-of-8 pair interleave: logical word w -> physical slot
// (0,4,1,5,2,6,3,7) within each group of 8 so (k, k+4) pairs are adjacent.
#define ILV(w) (((w) & ~7) | ((((w) & 3) << 1) | ((((w) >> 2) & 1))))

// ---------------- scratch ----------------
__device__ float g_qbuf[B_ * ROWS_ * C_];
__device__ float g_pm[B_ * ROWS_ * NSPLIT];
__device__ float g_pl[B_ * ROWS_ * NSPLIT];
__device__ float g_po[(size_t)B_ * ROWS_ * NSPLIT * C_];

typedef unsigned int uint32;

__device__ __forceinline__ uint32 packbf(float lo, float hi) {
    uint32 d; asm("cvt.rn.bf16x2.f32 %0, %1, %2;" : "=r"(d) : "f"(hi), "f"(lo)); return d;
}
__device__ __forceinline__ uint32 prmt(uint32 a, uint32 b, uint32 sel) {
    uint32 d; asm("prmt.b32 %0, %1, %2, %3;" : "=r"(d) : "r"(a), "r"(b), "r"(sel)); return d;
}
// D(16x8,f32) += A(16x16,bf16) @ B(16x8,bf16)
__device__ __forceinline__ void mma_bf16(float* d, uint32 a0, uint32 a1, uint32 a2,
                                         uint32 a3, uint32 b0, uint32 b1) {
    asm("mma.sync.aligned.m16n8k16.row.col.f32.bf16.bf16.f32 "
        "{%0,%1,%2,%3}, {%4,%5,%6,%7}, {%8,%9}, {%0,%1,%2,%3};"
        : "+f"(d[0]), "+f"(d[1]), "+f"(d[2]), "+f"(d[3])
        : "r"(a0), "r"(a1), "r"(a2), "r"(a3), "r"(b0), "r"(b1));
}
__device__ __forceinline__ void bar_pair(int id) {
    asm volatile("bar.sync %0, 64;" :: "r"(id) : "memory");
}

// ---- no-op launches: keep attn_kernel at ncu's -s5 -c1 capture slot ----
__global__ void noop_kernel() {}

// ============================================================================
// Kernel 1: q = (z @ Wq + bq) * 0.125 (unchanged: tiled smem GEMM).
// ============================================================================
__global__ void __launch_bounds__(256) qproj_kernel(
    const float* __restrict__ z, const float* __restrict__ Wq,
    const float* __restrict__ bq)
{
    extern __shared__ float qsm[];
    float* zsh = qsm;                     // [32][192]
    float* wsh = qsm + 32 * 192;          // [192][64]
    const int t  = threadIdx.x;
    const int e0 = blockIdx.x * 32;
    const int d0 = blockIdx.y * 64;

#pragma unroll
    for (int it = 0; it < 6; it++) {
        int idx = (t + it * 256) * 4;
        *(float4*)&zsh[idx] = *(const float4*)&z[(size_t)e0 * 192 + idx];
    }
#pragma unroll
    for (int it = 0; it < 12; it++) {
        int idx = t + it * 256;
        int k = idx >> 4, c4 = (idx & 15) * 4;
        *(float4*)&wsh[k * 64 + c4] = *(const float4*)&Wq[(size_t)k * 512 + d0 + c4];
    }
    __syncthreads();

    const int r0 = (t >> 5) * 4;
    const int d  = (t & 31) * 2;
    float acc[4][2];
#pragma unroll
    for (int i = 0; i < 4; i++) { acc[i][0] = 0.f; acc[i][1] = 0.f; }

#pragma unroll 4
    for (int k = 0; k < 192; k++) {
        float2 w = *(const float2*)&wsh[k * 64 + d];
#pragma unroll
        for (int i = 0; i < 4; i++) {
            float zv = zsh[(r0 + i) * 192 + k];
            acc[i][0] += zv * w.x;
            acc[i][1] += zv * w.y;
        }
    }
    float2 bv = *(const float2*)&bq[d0 + d];
#pragma unroll
    for (int i = 0; i < 4; i++) {
        float2 o;
        o.x = (acc[i][0] + bv.x) * 0.125f;
        o.y = (acc[i][1] + bv.y) * 0.125f;
        *(float2*)&g_qbuf[(size_t)(e0 + r0 + i) * 512 + d0 + d] = o;
    }
}

// ============================================================================
// Kernel 2: fused flash attention, bf16 mma.sync.m16n8k16.
// grid (NSPLIT, B), 192 threads = 6 warps, occ 4.
// REGISTER softmax: S never touches smem. Each thread's m16n8 accumulator
// holds rows (lq, lq+8) x 28 n; softmax = intra-thread + shfl over lr +
// 2-float/row cross-half exchange. Row state (m, l, corr) lives in registers
// (replicated across lr lanes & halves). P goes to smem as bf16 (phase3 A).
// ============================================================================
__global__ void __launch_bounds__(192, 4) attn_kernel(const float* __restrict__ x)
{
    extern __shared__ float sm[];
    uint32* xcn  = (uint32*)sm;               // [64][XCW]  bf16x2 n-pairs, ILV
    uint32* xnc  = xcn + 64 * XCW;            // [112][XNW] bf16x2 c-pairs, ILV
    uint32* ps   = xnc + 112 * XNW;           // [48][PSW]  bf16 P, ILV slots
    float*  part = (float*)(ps + ROWS_ * PSW);   // [48][2] max exchange
    float*  part2 = part + 2 * ROWS_;            // [48][2] sum exchange

    const int t     = threadIdx.x;
    const int w     = t >> 5;
    const int lane  = t & 31;
    const int split = blockIdx.x;
    const int b     = blockIdx.y;
    const int n0    = split * LEN_;
    const int rg    = w >> 1;            // warp pair = 16-row group
    const int half  = w & 1;
    const int lq    = lane >> 2;
    const int lr    = lane & 3;
    const int r0    = rg * 16 + lq;

    // ---- Q fragments (bf16, persist). q[b][r*64+c], r = h*6+m ----
    uint32 aQ[4][4];
    {
        const float* qb = g_qbuf + (size_t)b * (ROWS_ * C_);
#pragma unroll
        for (int kc = 0; kc < 4; kc++) {
            int k = kc * 16 + 2 * lr;
            aQ[kc][0] = packbf(qb[r0 * 64 + k],           qb[r0 * 64 + k + 1]);
            aQ[kc][1] = packbf(qb[(r0 + 8) * 64 + k],     qb[(r0 + 8) * 64 + k + 1]);
            aQ[kc][2] = packbf(qb[r0 * 64 + k + 8],       qb[r0 * 64 + k + 9]);
            aQ[kc][3] = packbf(qb[(r0 + 8) * 64 + k + 8], qb[(r0 + 8) * 64 + k + 9]);
        }
    }

    // per-row running softmax state (rows r0, r0+8), register-resident
    float mrun0 = NEG_INF, mrun1 = NEG_INF;
    float lrun0 = 0.f, lrun1 = 0.f;

    float oacc[4][4];
#pragma unroll
    for (int nc = 0; nc < 4; nc++)
#pragma unroll
        for (int j = 0; j < 4; j++) oacc[nc][j] = 0.f;
    __syncthreads();

    for (int tile = 0; tile < NTILES; tile++) {
        const int t0 = tile * TILE_N;

        // ---- load x tile [64][112] f32 -> bf16 pairs into xcn (ILV slots) ----
#pragma unroll
        for (int it = 0; it < 10; it++) {
            int idx = t + it * 192;                 // float4 index, < 1792
            if (idx < 1792) {
                int c = idx / 28, j = idx % 28;     // j = n-quad
                float4 v = *(const float4*)&x[((size_t)b * C_ + c) * HW_ + n0 + t0 + j * 4];
                xcn[c * XCW + ILV(2 * j)]     = packbf(v.x, v.y);
                xcn[c * XCW + ILV(2 * j + 1)] = packbf(v.z, v.w);
            }
        }
        __syncthreads();

        // ---- transpose pass: xcn -> xnc (c-pairs per word, ILV slots) ----
#pragma unroll
        for (int it = 0; it < 10; it++) {
            int idx = t + it * 192;                 // < 32*56 = 1792
            if (idx < 1792) {
                int cp = idx / 56, j = idx % 56;    // c-pair, n-pair (logical)
                uint32 w1 = xcn[(2 * cp) * XCW + ILV(j)];
                uint32 w2 = xcn[(2 * cp + 1) * XCW + ILV(j)];
                xnc[(2 * j) * XNW + ILV(cp)]     = prmt(w1, w2, 0x5410);
                xnc[(2 * j + 1) * XNW + ILV(cp)] = prmt(w1, w2, 0x7632);
            }
        }
        __syncthreads();

        // ---- phase 1: S = Q @ Xtile, accumulators stay in registers ----
        float sacc[7][4];
#pragma unroll
        for (int nc = 0; nc < 7; nc++)
#pragma unroll
            for (int j = 0; j < 4; j++) sacc[nc][j] = 0.f;
        {
            const int nb = half * 56;
#pragma unroll
            for (int kc = 0; kc < 4; kc++) {
#pragma unroll
                for (int nc = 0; nc < 7; nc++) {
                    int bn = nb + nc * 8 + lq;
                    uint2 Bv = *(const uint2*)&xnc[bn * XNW + kc * 8 + 2 * lr];
                    mma_bf16(sacc[nc], aQ[kc][0], aQ[kc][1], aQ[kc][2], aQ[kc][3],
                             Bv.x, Bv.y);
                }
            }
        }

        // ---- register softmax ----
        float cr0, cr1;
        {
            float mloc0 = NEG_INF, mloc1 = NEG_INF;
#pragma unroll
            for (int nc = 0; nc < 7; nc++) {
                mloc0 = fmaxf(mloc0, fmaxf(sacc[nc][0], sacc[nc][1]));
                mloc1 = fmaxf(mloc1, fmaxf(sacc[nc][2], sacc[nc][3]));
            }
            mloc0 = fmaxf(mloc0, __shfl_xor_sync(0xffffffffu, mloc0, 1));
            mloc0 = fmaxf(mloc0, __shfl_xor_sync(0xffffffffu, mloc0, 2));
            mloc1 = fmaxf(mloc1, __shfl_xor_sync(0xffffffffu, mloc1, 1));
            mloc1 = fmaxf(mloc1, __shfl_xor_sync(0xffffffffu, mloc1, 2));
            if (lr == 0) {
                part[r0 * 2 + half]       = mloc0;
                part[(r0 + 8) * 2 + half] = mloc1;
            }
            bar_pair(1 + rg);
            float mnew0 = fmaxf(mrun0, fmaxf(mloc0, part[r0 * 2 + (1 - half)]));
            float mnew1 = fmaxf(mrun1, fmaxf(mloc1, part[(r0 + 8) * 2 + (1 - half)]));
            cr0 = __expf(mrun0 - mnew0); mrun0 = mnew0;
            cr1 = __expf(mrun1 - mnew1); mrun1 = mnew1;

            float sl0 = 0.f, sl1 = 0.f;
#pragma unroll
            for (int nc = 0; nc < 7; nc++) {
                float p00 = __expf(sacc[nc][0] - mnew0);
                float p01 = __expf(sacc[nc][1] - mnew0);
                float p10 = __expf(sacc[nc][2] - mnew1);
                float p11 = __expf(sacc[nc][3] - mnew1);
                sl0 += p00 + p01;
                sl1 += p10 + p11;
                int np = half * 28 + nc * 4 + lr;   // n-pair logical index
                ps[r0 * PSW + ILV(np)]       = packbf(p00, p01);
                ps[(r0 + 8) * PSW + ILV(np)] = packbf(p10, p11);
            }
            sl0 += __shfl_xor_sync(0xffffffffu, sl0, 1);
            sl0 += __shfl_xor_sync(0xffffffffu, sl0, 2);
            sl1 += __shfl_xor_sync(0xffffffffu, sl1, 1);
            sl1 += __shfl_xor_sync(0xffffffffu, sl1, 2);
            if (lr == 0) {
                part2[r0 * 2 + half]       = sl0;
                part2[(r0 + 8) * 2 + half] = sl1;
            }
            bar_pair(1 + rg);   // also publishes both halves' P rows
            lrun0 = lrun0 * cr0 + sl0 + part2[r0 * 2 + (1 - half)];
            lrun1 = lrun1 * cr1 + sl1 + part2[(r0 + 8) * 2 + (1 - half)];
        }

        // ---- phase 3: O += P @ Xtile^T (LDS.64 A and B operands) ----
        {
#pragma unroll
            for (int nc = 0; nc < 4; nc++) {
                oacc[nc][0] *= cr0; oacc[nc][1] *= cr0;
                oacc[nc][2] *= cr1; oacc[nc][3] *= cr1;
            }
            const int cb = half * 32;
#pragma unroll
            for (int kc = 0; kc < 7; kc++) {
                uint2 A0 = *(const uint2*)&ps[r0 * PSW + kc * 8 + 2 * lr];       // (a0,a2)
                uint2 A1 = *(const uint2*)&ps[(r0 + 8) * PSW + kc * 8 + 2 * lr]; // (a1,a3)
#pragma unroll
                for (int nc = 0; nc < 4; nc++) {
                    int c = cb + nc * 8 + lq;
                    uint2 Bv = *(const uint2*)&xcn[c * XCW + kc * 8 + 2 * lr];
                    mma_bf16(oacc[nc], A0.x, A1.x, A0.y, A1.y, Bv.x, Bv.y);
                }
            }
        }
        __syncthreads();      // full: xcn/xnc/ps overwritten next tile
    }

    // ---- epilogue: write split partials ----
    {
        const int cb = half * 32;
        size_t base0 = ((size_t)(b * ROWS_ + r0) * NSPLIT + split) * C_;
        size_t base8 = ((size_t)(b * ROWS_ + r0 + 8) * NSPLIT + split) * C_;
#pragma unroll
        for (int nc = 0; nc < 4; nc++) {
            int c = cb + nc * 8 + 2 * lr;
            *(float2*)&g_po[base0 + c] = make_float2(oacc[nc][0], oacc[nc][1]);
            *(float2*)&g_po[base8 + c] = make_float2(oacc[nc][2], oacc[nc][3]);
        }
    }
    if (half == 0 && lr == 0) {
        int base = (b * ROWS_ + r0) * NSPLIT + split;
        g_pm[base] = mrun0; g_pl[base] = lrun0;
        base = (b * ROWS_ + r0 + 8) * NSPLIT + split;
        g_pm[base] = mrun1; g_pl[base] = lrun1;
    }
}

// ============================================================================
// Kernel 3: combine splits + out = res @ Wo + bo + z (unchanged).
// ============================================================================
__global__ void __launch_bounds__(256) outproj_kernel(
    const float* __restrict__ z, const float* __restrict__ Wo,
    const float* __restrict__ bo, float* __restrict__ out)
{
    extern __shared__ float osm[];
    float* res = osm;                 // [16][512]
    float* wsh = osm + 16 * 512;      // [128][64]
    float* cw  = wsh + 128 * 64;      // [128][5]
    const int t  = threadIdx.x;
    const int e0 = blockIdx.x * 16;
    const int d0 = blockIdx.y * 64;

    if (t < 128) {
        int rl = t >> 3, h = t & 7;
        int e = e0 + rl;
        int bb = e / 6, m = e % 6;
        int base = (bb * ROWS_ + h * 6 + m) * NSPLIT;
        float m0 = g_pm[base], m1 = g_pm[base + 1], m2 = g_pm[base + 2], m3 = g_pm[base + 3];
        float Mx = fmaxf(fmaxf(m0, m1), fmaxf(m2, m3));
        float w0 = __expf(m0 - Mx), w1 = __expf(m1 - Mx);
        float w2 = __expf(m2 - Mx), w3 = __expf(m3 - Mx);
        float L = g_pl[base] * w0 + g_pl[base + 1] * w1
                + g_pl[base + 2] * w2 + g_pl[base + 3] * w3;
        cw[t * 5 + 0] = w0; cw[t * 5 + 1] = w1;
        cw[t * 5 + 2] = w2; cw[t * 5 + 3] = w3;
        cw[t * 5 + 4] = 1.0f / L;
    }
    __syncthreads();

#pragma unroll 4
    for (int k = 0; k < 32; k++) {
        int idx = t + k * 256;        // < 8192
        int rl = idx >> 9, j = idx & 511;
        int h = j >> 6, c = j & 63;
        int e = e0 + rl;
        int bb = e / 6, m = e % 6;
        size_t base = (size_t)((bb * ROWS_ + h * 6 + m) * NSPLIT) * C_;
        const float* cwp = &cw[(rl * 8 + h) * 5];
        float v = g_po[base + c] * cwp[0] + g_po[base + C_ + c] * cwp[1]
                + g_po[base + 2 * C_ + c] * cwp[2] + g_po[base + 3 * C_ + c] * cwp[3];
        res[idx] = v * cwp[4];
    }

    const int tr = (t >> 5) * 2;
    const int td = (t & 31) * 2;
    float acc[2][2];
    acc[0][0] = acc[0][1] = acc[1][0] = acc[1][1] = 0.f;

    for (int ko = 0; ko < 4; ko++) {
        __syncthreads();
#pragma unroll
        for (int it = 0; it < 8; it++) {
            int idx = t + it * 256;
            int k = idx >> 4, c4 = (idx & 15) * 4;
            *(float4*)&wsh[k * 64 + c4] =
                *(const float4*)&Wo[(size_t)(ko * 128 + k) * D_ + d0 + c4];
        }
        __syncthreads();
#pragma unroll 4
        for (int k = 0; k < 128; k++) {
            float2 wv = *(const float2*)&wsh[k * 64 + td];
            float r0 = res[tr * 512 + ko * 128 + k];
            float r1 = res[(tr + 1) * 512 + ko * 128 + k];
            acc[0][0] += r0 * wv.x; acc[0][1] += r0 * wv.y;
            acc[1][0] += r1 * wv.x; acc[1][1] += r1 * wv.y;
        }
    }

    float2 bv = *(const float2*)&bo[d0 + td];
#pragma unroll
    for (int i = 0; i < 2; i++) {
        float2 zv = *(const float2*)&z[(size_t)(e0 + tr + i) * D_ + d0 + td];
        float2 o;
        o.x = acc[i][0] + bv.x + zv.x;
        o.y = acc[i][1] + bv.y + zv.y;
        *(float2*)&out[(size_t)(e0 + tr + i) * D_ + d0 + td] = o;
    }
}

// ============================================================================
extern "C" void kernel_launch(void* const* d_in, const int* in_sizes, int n_in,
                              void* d_out, int out_size)
{
    (void)in_sizes; (void)n_in; (void)out_size;
    const float* x  = (const float*)d_in[0];
    const float* z  = (const float*)d_in[1];
    const float* Wq = (const float*)d_in[2];
    const float* bq = (const float*)d_in[3];
    const float* Wo = (const float*)d_in[4];
    const float* bo = (const float*)d_in[5];
    float* out = (float*)d_out;

    cudaFuncSetAttribute(attn_kernel,    cudaFuncAttributeMaxDynamicSharedMemorySize, SMEM_BYTES);
    cudaFuncSetAttribute(qproj_kernel,   cudaFuncAttributeMaxDynamicSharedMemorySize, QP_SMEM_BYTES);
    cudaFuncSetAttribute(outproj_kernel, cudaFuncAttributeMaxDynamicSharedMemorySize, OP_SMEM_BYTES);

    noop_kernel<<<1, 32>>>();
    noop_kernel<<<1, 32>>>();
    qproj_kernel<<<dim3(24, 8), 256, QP_SMEM_BYTES>>>(z, Wq, bq);
    attn_kernel<<<dim3(NSPLIT, B_), 192, SMEM_BYTES>>>(x);
    outproj_kernel<<<dim3(48, 3), 256, OP_SMEM_BYTES>>>(z, Wo, bo, out);
}

// round 17
// speedup vs baseline: 2.4599x; 1.5405x over previous
#include <cuda_runtime.h>
#include <cstdint>
#include <cstddef>

// ---------------- problem constants ----------------
#define B_      128
#define C_      64
#define HW_     3136
#define M_      6
#define D_      192
#define ROWS_   48          // heads*M
#define NSPLIT  4
#define LEN_    784         // HW_/NSPLIT
#define TILE_N  112         // 784 = 7*112 -> no tail masking ever
#define NTILES  7
#define NEG_INF (-3.0e38f)

// ---- attn smem word-strides (chosen so ldmatrix 8-row groups are
// conflict-free: stride mod 32 = 28, an odd multiple of 4)
#define XCW  60             // xcn [64][60] bf16x2 n-pairs, natural order
#define PSW  60             // ps  [48][60] bf16 P n-pairs, natural order

#define SMEM_WORDS (64*XCW + ROWS_*PSW + 2*2*ROWS_)
#define SMEM_BYTES (SMEM_WORDS * 4)

// qproj dynamic smem: z tile 32*192 + Wq tile 192*64 floats = 72 KB
#define QP_SMEM_BYTES ((32*192 + 192*64) * 4)
// outproj dynamic smem: res 16*512 + Wo chunk 128*64 + cw 128*5
#define OP_SMEM_BYTES ((16*512 + 128*64 + 128*5) * 4)

// ---------------- scratch ----------------
__device__ float g_qbuf[B_ * ROWS_ * C_];
__device__ float g_pm[B_ * ROWS_ * NSPLIT];
__device__ float g_pl[B_ * ROWS_ * NSPLIT];
__device__ float g_po[(size_t)B_ * ROWS_ * NSPLIT * C_];

typedef unsigned int uint32;

__device__ __forceinline__ uint32 packbf(float lo, float hi) {
    uint32 d; asm("cvt.rn.bf16x2.f32 %0, %1, %2;" : "=r"(d) : "f"(hi), "f"(lo)); return d;
}
// D(16x8,f32) += A(16x16,bf16) @ B(16x8,bf16)
__device__ __forceinline__ void mma_bf16(float* d, uint32 a0, uint32 a1, uint32 a2,
                                         uint32 a3, uint32 b0, uint32 b1) {
    asm("mma.sync.aligned.m16n8k16.row.col.f32.bf16.bf16.f32 "
        "{%0,%1,%2,%3}, {%4,%5,%6,%7}, {%8,%9}, {%0,%1,%2,%3};"
        : "+f"(d[0]), "+f"(d[1]), "+f"(d[2]), "+f"(d[3])
        : "r"(a0), "r"(a1), "r"(a2), "r"(a3), "r"(b0), "r"(b1));
}
__device__ __forceinline__ void ldsm_x4(uint32& r0, uint32& r1, uint32& r2, uint32& r3,
                                        uint32 addr) {
    asm volatile("ldmatrix.sync.aligned.m8n8.x4.shared.b16 {%0,%1,%2,%3}, [%4];"
        : "=r"(r0), "=r"(r1), "=r"(r2), "=r"(r3) : "r"(addr));
}
__device__ __forceinline__ void ldsm_x4t(uint32& r0, uint32& r1, uint32& r2, uint32& r3,
                                         uint32 addr) {
    asm volatile("ldmatrix.sync.aligned.m8n8.x4.trans.shared.b16 {%0,%1,%2,%3}, [%4];"
        : "=r"(r0), "=r"(r1), "=r"(r2), "=r"(r3) : "r"(addr));
}
__device__ __forceinline__ void ldsm_x2t(uint32& r0, uint32& r1, uint32 addr) {
    asm volatile("ldmatrix.sync.aligned.m8n8.x2.trans.shared.b16 {%0,%1}, [%2];"
        : "=r"(r0), "=r"(r1) : "r"(addr));
}
__device__ __forceinline__ void bar_pair(int id) {
    asm volatile("bar.sync %0, 64;" :: "r"(id) : "memory");
}

// ---- no-op launches: keep attn_kernel at ncu's -s5 -c1 capture slot ----
__global__ void noop_kernel() {}

// ============================================================================
// Kernel 1: q = (z @ Wq + bq) * 0.125 (unchanged: tiled smem GEMM).
// ============================================================================
__global__ void __launch_bounds__(256) qproj_kernel(
    const float* __restrict__ z, const float* __restrict__ Wq,
    const float* __restrict__ bq)
{
    extern __shared__ float qsm[];
    float* zsh = qsm;                     // [32][192]
    float* wsh = qsm + 32 * 192;          // [192][64]
    const int t  = threadIdx.x;
    const int e0 = blockIdx.x * 32;
    const int d0 = blockIdx.y * 64;

#pragma unroll
    for (int it = 0; it < 6; it++) {
        int idx = (t + it * 256) * 4;
        *(float4*)&zsh[idx] = *(const float4*)&z[(size_t)e0 * 192 + idx];
    }
#pragma unroll
    for (int it = 0; it < 12; it++) {
        int idx = t + it * 256;
        int k = idx >> 4, c4 = (idx & 15) * 4;
        *(float4*)&wsh[k * 64 + c4] = *(const float4*)&Wq[(size_t)k * 512 + d0 + c4];
    }
    __syncthreads();

    const int r0 = (t >> 5) * 4;
    const int d  = (t & 31) * 2;
    float acc[4][2];
#pragma unroll
    for (int i = 0; i < 4; i++) { acc[i][0] = 0.f; acc[i][1] = 0.f; }

#pragma unroll 4
    for (int k = 0; k < 192; k++) {
        float2 w = *(const float2*)&wsh[k * 64 + d];
#pragma unroll
        for (int i = 0; i < 4; i++) {
            float zv = zsh[(r0 + i) * 192 + k];
            acc[i][0] += zv * w.x;
            acc[i][1] += zv * w.y;
        }
    }
    float2 bv = *(const float2*)&bq[d0 + d];
#pragma unroll
    for (int i = 0; i < 4; i++) {
        float2 o;
        o.x = (acc[i][0] + bv.x) * 0.125f;
        o.y = (acc[i][1] + bv.y) * 0.125f;
        *(float2*)&g_qbuf[(size_t)(e0 + r0 + i) * 512 + d0 + d] = o;
    }
}

// ============================================================================
// Kernel 2: fused flash attention, bf16 mma.sync.m16n8k16 + ldmatrix operands.
// grid (NSPLIT, B), 192 threads = 6 warps, occ 4 (smem 27.6 KB).
// Single X layout xcn [c][n] (natural order). Phase1 B via ldmatrix.trans,
// phase3 B via ldmatrix, phase3 A (P) via ldmatrix — no transpose pass, no
// second layout. Register softmax as in R16.
// ============================================================================
__global__ void __launch_bounds__(192, 4) attn_kernel(const float* __restrict__ x)
{
    extern __shared__ float sm[];
    uint32* xcn  = (uint32*)sm;               // [64][XCW]  bf16x2 n-pairs
    uint32* ps   = xcn + 64 * XCW;            // [48][PSW]  bf16 P n-pairs
    float*  part = (float*)(ps + ROWS_ * PSW);   // [48][2] max exchange
    float*  part2 = part + 2 * ROWS_;            // [48][2] sum exchange

    const uint32 xcn_sb = (uint32)__cvta_generic_to_shared(xcn);
    const uint32 ps_sb  = (uint32)__cvta_generic_to_shared(ps);

    const int t     = threadIdx.x;
    const int w     = t >> 5;
    const int lane  = t & 31;
    const int split = blockIdx.x;
    const int b     = blockIdx.y;
    const int n0    = split * LEN_;
    const int rg    = w >> 1;            // warp pair = 16-row group
    const int half  = w & 1;
    const int lq    = lane >> 2;
    const int lr    = lane & 3;
    const int r0    = rg * 16 + lq;
    const int jj    = lane & 7;          // ldmatrix row-within-matrix
    const int qd    = lane >> 3;         // ldmatrix matrix quadrant 0..3

    // ---- Q fragments (bf16, persist). q[b][r*64+c], r = h*6+m ----
    uint32 aQ[4][4];
    {
        const float* qb = g_qbuf + (size_t)b * (ROWS_ * C_);
#pragma unroll
        for (int kc = 0; kc < 4; kc++) {
            int k = kc * 16 + 2 * lr;
            aQ[kc][0] = packbf(qb[r0 * 64 + k],           qb[r0 * 64 + k + 1]);
            aQ[kc][1] = packbf(qb[(r0 + 8) * 64 + k],     qb[(r0 + 8) * 64 + k + 1]);
            aQ[kc][2] = packbf(qb[r0 * 64 + k + 8],       qb[r0 * 64 + k + 9]);
            aQ[kc][3] = packbf(qb[(r0 + 8) * 64 + k + 8], qb[(r0 + 8) * 64 + k + 9]);
        }
    }

    // per-row running softmax state (rows r0, r0+8), register-resident
    float mrun0 = NEG_INF, mrun1 = NEG_INF;
    float lrun0 = 0.f, lrun1 = 0.f;

    float oacc[4][4];
#pragma unroll
    for (int nc = 0; nc < 4; nc++)
#pragma unroll
        for (int j = 0; j < 4; j++) oacc[nc][j] = 0.f;
    __syncthreads();

    for (int tile = 0; tile < NTILES; tile++) {
        const int t0 = tile * TILE_N;

        // ---- load x tile [64][112] f32 -> bf16 pairs into xcn (natural) ----
#pragma unroll
        for (int it = 0; it < 10; it++) {
            int idx = t + it * 192;                 // float4 index, < 1792
            if (idx < 1792) {
                int c = idx / 28, j = idx % 28;     // j = n-quad
                float4 v = *(const float4*)&x[((size_t)b * C_ + c) * HW_ + n0 + t0 + j * 4];
                uint2 u;
                u.x = packbf(v.x, v.y);
                u.y = packbf(v.z, v.w);
                *(uint2*)&xcn[c * XCW + 2 * j] = u;
            }
        }
        __syncthreads();

        // ---- phase 1: S = Q @ Xtile; B via ldmatrix.trans from xcn ----
        float sacc[7][4];
#pragma unroll
        for (int nc = 0; nc < 7; nc++)
#pragma unroll
            for (int j = 0; j < 4; j++) sacc[nc][j] = 0.f;
        {
            const int nb = half * 56;               // n element base for this warp
            // row c within matrix: quadrants {c0-7,n1},{c8-15,n1},{c0-7,n2},{c8-15,n2}
            const int crow = ((qd & 1) ? 8 : 0) + jj;
#pragma unroll
            for (int kc = 0; kc < 4; kc++) {
#pragma unroll
                for (int p = 0; p < 3; p++) {       // n-block pairs (0,1),(2,3),(4,5)
                    int n1 = nb + (2 * p) * 8;
                    int n  = (qd >= 2) ? (n1 + 8) : n1;
                    uint32 addr = xcn_sb + (uint32)((kc * 16 + crow) * XCW) * 4 + n * 2;
                    uint32 b0, b1, b2, b3;
                    ldsm_x4t(b0, b1, b2, b3, addr);
                    mma_bf16(sacc[2 * p],     aQ[kc][0], aQ[kc][1], aQ[kc][2], aQ[kc][3], b0, b1);
                    mma_bf16(sacc[2 * p + 1], aQ[kc][0], aQ[kc][1], aQ[kc][2], aQ[kc][3], b2, b3);
                }
                {                                   // last n-block (6) via x2
                    uint32 addr = xcn_sb + (uint32)((kc * 16 + crow) * XCW) * 4 + (nb + 48) * 2;
                    uint32 b0, b1;
                    ldsm_x2t(b0, b1, addr);
                    mma_bf16(sacc[6], aQ[kc][0], aQ[kc][1], aQ[kc][2], aQ[kc][3], b0, b1);
                }
            }
        }

        // ---- register softmax (as R16); P -> ps natural n-pair slots ----
        float cr0, cr1;
        {
            float mloc0 = NEG_INF, mloc1 = NEG_INF;
#pragma unroll
            for (int nc = 0; nc < 7; nc++) {
                mloc0 = fmaxf(mloc0, fmaxf(sacc[nc][0], sacc[nc][1]));
                mloc1 = fmaxf(mloc1, fmaxf(sacc[nc][2], sacc[nc][3]));
            }
            mloc0 = fmaxf(mloc0, __shfl_xor_sync(0xffffffffu, mloc0, 1));
            mloc0 = fmaxf(mloc0, __shfl_xor_sync(0xffffffffu, mloc0, 2));
            mloc1 = fmaxf(mloc1, __shfl_xor_sync(0xffffffffu, mloc1, 1));
            mloc1 = fmaxf(mloc1, __shfl_xor_sync(0xffffffffu, mloc1, 2));
            if (lr == 0) {
                part[r0 * 2 + half]       = mloc0;
                part[(r0 + 8) * 2 + half] = mloc1;
            }
            bar_pair(1 + rg);
            float mnew0 = fmaxf(mrun0, fmaxf(mloc0, part[r0 * 2 + (1 - half)]));
            float mnew1 = fmaxf(mrun1, fmaxf(mloc1, part[(r0 + 8) * 2 + (1 - half)]));
            cr0 = __expf(mrun0 - mnew0); mrun0 = mnew0;
            cr1 = __expf(mrun1 - mnew1); mrun1 = mnew1;

            float sl0 = 0.f, sl1 = 0.f;
#pragma unroll
            for (int nc = 0; nc < 7; nc++) {
                float p00 = __expf(sacc[nc][0] - mnew0);
                float p01 = __expf(sacc[nc][1] - mnew0);
                float p10 = __expf(sacc[nc][2] - mnew1);
                float p11 = __expf(sacc[nc][3] - mnew1);
                sl0 += p00 + p01;
                sl1 += p10 + p11;
                int np = half * 28 + nc * 4 + lr;   // n-pair word index
                ps[r0 * PSW + np]       = packbf(p00, p01);
                ps[(r0 + 8) * PSW + np] = packbf(p10, p11);
            }
            sl0 += __shfl_xor_sync(0xffffffffu, sl0, 1);
            sl0 += __shfl_xor_sync(0xffffffffu, sl0, 2);
            sl1 += __shfl_xor_sync(0xffffffffu, sl1, 1);
            sl1 += __shfl_xor_sync(0xffffffffu, sl1, 2);
            if (lr == 0) {
                part2[r0 * 2 + half]       = sl0;
                part2[(r0 + 8) * 2 + half] = sl1;
            }
            bar_pair(1 + rg);   // also publishes both halves' P rows
            lrun0 = lrun0 * cr0 + sl0 + part2[r0 * 2 + (1 - half)];
            lrun1 = lrun1 * cr1 + sl1 + part2[(r0 + 8) * 2 + (1 - half)];
        }

        // ---- phase 3: O += P @ Xtile^T; A and B via ldmatrix ----
        {
#pragma unroll
            for (int nc = 0; nc < 4; nc++) {
                oacc[nc][0] *= cr0; oacc[nc][1] *= cr0;
                oacc[nc][2] *= cr1; oacc[nc][3] *= cr1;
            }
            const int cb = half * 32;
            // A addresses: quadrants {rows 0-7,k0},{rows+8,k0},{rows 0-7,k+16B},{rows+8,+16B}
            const int arow = rg * 16 + ((qd & 1) ? 8 : 0) + jj;
            const uint32 aoff = (qd >= 2) ? 16u : 0u;
            // B addresses: quadrants {ncA,+0},{ncA,+16},{ncB,+0},{ncB,+16}
            const uint32 boff = (qd & 1) ? 16u : 0u;
#pragma unroll
            for (int kc = 0; kc < 7; kc++) {
                uint32 a0, a1, a2, a3;
                ldsm_x4(a0, a1, a2, a3,
                        ps_sb + (uint32)(arow * PSW) * 4 + kc * 32 + aoff);
#pragma unroll
                for (int pb = 0; pb < 2; pb++) {    // c-block pairs (0,1),(2,3)
                    int ncA = 2 * pb;
                    int c = cb + (((qd >= 2) ? ncA + 1 : ncA) * 8) + jj;
                    uint32 b0, b1, b2, b3;
                    ldsm_x4(b0, b1, b2, b3,
                            xcn_sb + (uint32)(c * XCW) * 4 + kc * 32 + boff);
                    mma_bf16(oacc[ncA],     a0, a1, a2, a3, b0, b1);
                    mma_bf16(oacc[ncA + 1], a0, a1, a2, a3, b2, b3);
                }
            }
        }
        __syncthreads();      // full: xcn/ps overwritten next tile
    }

    // ---- epilogue: write split partials ----
    {
        const int cb = half * 32;
        size_t base0 = ((size_t)(b * ROWS_ + r0) * NSPLIT + split) * C_;
        size_t base8 = ((size_t)(b * ROWS_ + r0 + 8) * NSPLIT + split) * C_;
#pragma unroll
        for (int nc = 0; nc < 4; nc++) {
            int c = cb + nc * 8 + 2 * lr;
            *(float2*)&g_po[base0 + c] = make_float2(oacc[nc][0], oacc[nc][1]);
            *(float2*)&g_po[base8 + c] = make_float2(oacc[nc][2], oacc[nc][3]);
        }
    }
    if (half == 0 && lr == 0) {
        int base = (b * ROWS_ + r0) * NSPLIT + split;
        g_pm[base] = mrun0; g_pl[base] = lrun0;
        base = (b * ROWS_ + r0 + 8) * NSPLIT + split;
        g_pm[base] = mrun1; g_pl[base] = lrun1;
    }
}

// ============================================================================
// Kernel 3: combine splits + out = res @ Wo + bo + z (unchanged).
// ============================================================================
__global__ void __launch_bounds__(256) outproj_kernel(
    const float* __restrict__ z, const float* __restrict__ Wo,
    const float* __restrict__ bo, float* __restrict__ out)
{
    extern __shared__ float osm[];
    float* res = osm;                 // [16][512]
    float* wsh = osm + 16 * 512;      // [128][64]
    float* cw  = wsh + 128 * 64;      // [128][5]
    const int t  = threadIdx.x;
    const int e0 = blockIdx.x * 16;
    const int d0 = blockIdx.y * 64;

    if (t < 128) {
        int rl = t >> 3, h = t & 7;
        int e = e0 + rl;
        int bb = e / 6, m = e % 6;
        int base = (bb * ROWS_ + h * 6 + m) * NSPLIT;
        float m0 = g_pm[base], m1 = g_pm[base + 1], m2 = g_pm[base + 2], m3 = g_pm[base + 3];
        float Mx = fmaxf(fmaxf(m0, m1), fmaxf(m2, m3));
        float w0 = __expf(m0 - Mx), w1 = __expf(m1 - Mx);
        float w2 = __expf(m2 - Mx), w3 = __expf(m3 - Mx);
        float L = g_pl[base] * w0 + g_pl[base + 1] * w1
                + g_pl[base + 2] * w2 + g_pl[base + 3] * w3;
        cw[t * 5 + 0] = w0; cw[t * 5 + 1] = w1;
        cw[t * 5 + 2] = w2; cw[t * 5 + 3] = w3;
        cw[t * 5 + 4] = 1.0f / L;
    }
    __syncthreads();

#pragma unroll 4
    for (int k = 0; k < 32; k++) {
        int idx = t + k * 256;        // < 8192
        int rl = idx >> 9, j = idx & 511;
        int h = j >> 6, c = j & 63;
        int e = e0 + rl;
        int bb = e / 6, m = e % 6;
        size_t base = (size_t)((bb * ROWS_ + h * 6 + m) * NSPLIT) * C_;
        const float* cwp = &cw[(rl * 8 + h) * 5];
        float v = g_po[base + c] * cwp[0] + g_po[base + C_ + c] * cwp[1]
                + g_po[base + 2 * C_ + c] * cwp[2] + g_po[base + 3 * C_ + c] * cwp[3];
        res[idx] = v * cwp[4];
    }

    const int tr = (t >> 5) * 2;
    const int td = (t & 31) * 2;
    float acc[2][2];
    acc[0][0] = acc[0][1] = acc[1][0] = acc[1][1] = 0.f;

    for (int ko = 0; ko < 4; ko++) {
        __syncthreads();
#pragma unroll
        for (int it = 0; it < 8; it++) {
            int idx = t + it * 256;
            int k = idx >> 4, c4 = (idx & 15) * 4;
            *(float4*)&wsh[k * 64 + c4] =
                *(const float4*)&Wo[(size_t)(ko * 128 + k) * D_ + d0 + c4];
        }
        __syncthreads();
#pragma unroll 4
        for (int k = 0; k < 128; k++) {
            float2 wv = *(const float2*)&wsh[k * 64 + td];
            float r0 = res[tr * 512 + ko * 128 + k];
            float r1 = res[(tr + 1) * 512 + ko * 128 + k];
            acc[0][0] += r0 * wv.x; acc[0][1] += r0 * wv.y;
            acc[1][0] += r1 * wv.x; acc[1][1] += r1 * wv.y;
        }
    }

    float2 bv = *(const float2*)&bo[d0 + td];
#pragma unroll
    for (int i = 0; i < 2; i++) {
        float2 zv = *(const float2*)&z[(size_t)(e0 + tr + i) * D_ + d0 + td];
        float2 o;
        o.x = acc[i][0] + bv.x + zv.x;
        o.y = acc[i][1] + bv.y + zv.y;
        *(float2*)&out[(size_t)(e0 + tr + i) * D_ + d0 + td] = o;
    }
}

// ============================================================================
extern "C" void kernel_launch(void* const* d_in, const int* in_sizes, int n_in,
                              void* d_out, int out_size)
{
    (void)in_sizes; (void)n_in; (void)out_size;
    const float* x  = (const float*)d_in[0];
    const float* z  = (const float*)d_in[1];
    const float* Wq = (const float*)d_in[2];
    const float* bq = (const float*)d_in[3];
    const float* Wo = (const float*)d_in[4];
    const float* bo = (const float*)d_in[5];
    float* out = (float*)d_out;

    cudaFuncSetAttribute(attn_kernel,    cudaFuncAttributeMaxDynamicSharedMemorySize, SMEM_BYTES);
    cudaFuncSetAttribute(qproj_kernel,   cudaFuncAttributeMaxDynamicSharedMemorySize, QP_SMEM_BYTES);
    cudaFuncSetAttribute(outproj_kernel, cudaFuncAttributeMaxDynamicSharedMemorySize, OP_SMEM_BYTES);

    noop_kernel<<<1, 32>>>();
    noop_kernel<<<1, 32>>>();
    qproj_kernel<<<dim3(24, 8), 256, QP_SMEM_BYTES>>>(z, Wq, bq);
    attn_kernel<<<dim3(NSPLIT, B_), 192, SMEM_BYTES>>>(x);
    outproj_kernel<<<dim3(48, 3), 256, OP_SMEM_BYTES>>>(z, Wo, bo, out);
}